// round 2
// baseline (speedup 1.0000x reference)
#include <cuda_runtime.h>
#include <math.h>

// ----------------------------------------------------------------------------
// Problem constants
// ----------------------------------------------------------------------------
#define BB 4
#define SS 2048
#define DD 1024
#define HH 16
#define DK 64
#define DV 64
#define BS (BB * SS)            // 8192 rows
#define NELEM (BS * DD)         // 8388608

// ----------------------------------------------------------------------------
// Device scratch (static globals: allocation-free)
// ----------------------------------------------------------------------------
__device__ float g_qp[NELEM];   // Q projection (also the residual)
__device__ float g_kp[NELEM];   // K projection
__device__ float g_vp[NELEM];   // V projection
__device__ float g_ctx[NELEM];  // attention context, [B,S,H*DV] layout
__device__ float g_x[NELEM];    // fc out + residual (pre-LN)

// ----------------------------------------------------------------------------
// SGEMM: C[8192,1024] = A[8192,1024] @ W[1024,1024] + bias (+ res)
// 128x128 block, BK=8, 256 threads, 8x8 per thread (4+4 split tiling)
// ----------------------------------------------------------------------------
__global__ __launch_bounds__(256) void sgemm128(
    const float* __restrict__ A, const float* __restrict__ W,
    const float* __restrict__ bias, const float* __restrict__ res,
    float* __restrict__ C)
{
    __shared__ float As[8][128];
    __shared__ float Bs[8][128];

    const int tid  = threadIdx.x;
    const int row0 = blockIdx.y * 128;
    const int col0 = blockIdx.x * 128;

    const int arow = tid >> 1;          // 0..127
    const int apos = (tid & 1) * 4;     // 0 or 4
    const int brow = tid >> 5;          // 0..7
    const int bcol = (tid & 31) * 4;    // 0..124
    const int tr   = tid >> 4;          // 0..15
    const int tc   = tid & 15;          // 0..15

    float acc[8][8];
#pragma unroll
    for (int i = 0; i < 8; i++)
#pragma unroll
        for (int j = 0; j < 8; j++) acc[i][j] = 0.f;

    const float* Aptr = A + (size_t)(row0 + arow) * DD + apos;
    const float* Wptr = W + (size_t)brow * DD + col0 + bcol;

    for (int k0 = 0; k0 < DD; k0 += 8) {
        float4 a4 = *(const float4*)(Aptr + k0);
        float4 b4 = *(const float4*)(Wptr + (size_t)k0 * DD);
        __syncthreads();
        As[apos + 0][arow] = a4.x;
        As[apos + 1][arow] = a4.y;
        As[apos + 2][arow] = a4.z;
        As[apos + 3][arow] = a4.w;
        *(float4*)&Bs[brow][bcol] = b4;
        __syncthreads();
#pragma unroll
        for (int kk = 0; kk < 8; kk++) {
            float ra[8], rb[8];
            *(float4*)(ra + 0) = *(const float4*)&As[kk][tr * 4];
            *(float4*)(ra + 4) = *(const float4*)&As[kk][64 + tr * 4];
            *(float4*)(rb + 0) = *(const float4*)&Bs[kk][tc * 4];
            *(float4*)(rb + 4) = *(const float4*)&Bs[kk][64 + tc * 4];
#pragma unroll
            for (int i = 0; i < 8; i++)
#pragma unroll
                for (int j = 0; j < 8; j++) acc[i][j] += ra[i] * rb[j];
        }
    }

    const int cb0 = col0 + tc * 4;
    const float4 bias0 = *(const float4*)(bias + cb0);
    const float4 bias1 = *(const float4*)(bias + cb0 + 64);

#pragma unroll
    for (int i = 0; i < 8; i++) {
        const int r = row0 + tr * 4 + ((i < 4) ? i : (60 + i));
        float* crow = C + (size_t)r * DD;
        float4 o0, o1;
        o0.x = acc[i][0] + bias0.x; o0.y = acc[i][1] + bias0.y;
        o0.z = acc[i][2] + bias0.z; o0.w = acc[i][3] + bias0.w;
        o1.x = acc[i][4] + bias1.x; o1.y = acc[i][5] + bias1.y;
        o1.z = acc[i][6] + bias1.z; o1.w = acc[i][7] + bias1.w;
        if (res) {
            const float* rrow = res + (size_t)r * DD;
            float4 r0 = *(const float4*)(rrow + cb0);
            float4 r1 = *(const float4*)(rrow + cb0 + 64);
            o0.x += r0.x; o0.y += r0.y; o0.z += r0.z; o0.w += r0.w;
            o1.x += r1.x; o1.y += r1.y; o1.z += r1.z; o1.w += r1.w;
        }
        *(float4*)(crow + cb0)      = o0;
        *(float4*)(crow + cb0 + 64) = o1;
    }
}

// ----------------------------------------------------------------------------
// Flash attention (fp32). One block = (b*H+h, 64-row q tile).
// 256 threads, each owns a 4x4 tile of the 64x64 score block.
// ----------------------------------------------------------------------------
#define APITCH 68
#define ASMEM_FLOATS (3 * 64 * APITCH)
#define ASMEM_BYTES (ASMEM_FLOATS * 4)

__device__ __forceinline__ void att_load_tile(
    float* __restrict__ dst, const float* __restrict__ src, int row0)
{
    const int tid = threadIdx.x;
    const int r = tid >> 2;             // 0..63
    const int c = (tid & 3) * 16;       // 0,16,32,48
    const float* p = src + (size_t)(row0 + r) * DD + c;
#pragma unroll
    for (int u = 0; u < 4; u++) {
        float4 val = *(const float4*)(p + 4 * u);
        *(float4*)&dst[r * APITCH + c + 4 * u] = val;
    }
}

__global__ __launch_bounds__(256) void attn_kernel(
    const float* __restrict__ QP, const float* __restrict__ KP,
    const float* __restrict__ VP, float* __restrict__ CTX)
{
    extern __shared__ float smem[];
    float* Qs  = smem;
    float* KVs = smem + 64 * APITCH;
    float* Ps  = smem + 2 * 64 * APITCH;

    const int tid = threadIdx.x;
    const int bh = blockIdx.y;
    const int b = bh >> 4;
    const int h = bh & 15;
    const int q0 = blockIdx.x * 64;
    const int ty = tid >> 4;   // 0..15 -> q rows ty*4..
    const int tx = tid & 15;   // 0..15 -> cols tx*4..

    const size_t headoff = (size_t)b * SS * DD + (size_t)h * 64;
    const float* Qbase = QP + headoff;
    const float* Kbase = KP + headoff;
    const float* Vbase = VP + headoff;

    att_load_tile(Qs, Qbase, q0);

    float o[4][4];
    float m[4], l[4];
#pragma unroll
    for (int i = 0; i < 4; i++) {
        m[i] = -INFINITY; l[i] = 0.f;
#pragma unroll
        for (int j = 0; j < 4; j++) o[i][j] = 0.f;
    }

    for (int kt = 0; kt < SS / 64; kt++) {
        __syncthreads();                      // protect KVs/Ps from prev iter
        att_load_tile(KVs, Kbase, kt * 64);
        __syncthreads();

        // S = Q K^T (64x64x64), each thread a 4x4 tile
        float s[4][4];
#pragma unroll
        for (int i = 0; i < 4; i++)
#pragma unroll
            for (int j = 0; j < 4; j++) s[i][j] = 0.f;
#pragma unroll
        for (int d4 = 0; d4 < 16; d4++) {
            float4 qa[4], kb[4];
#pragma unroll
            for (int i = 0; i < 4; i++)
                qa[i] = *(const float4*)&Qs[(ty * 4 + i) * APITCH + d4 * 4];
#pragma unroll
            for (int j = 0; j < 4; j++)
                kb[j] = *(const float4*)&KVs[(tx * 4 + j) * APITCH + d4 * 4];
#pragma unroll
            for (int i = 0; i < 4; i++)
#pragma unroll
                for (int j = 0; j < 4; j++)
                    s[i][j] += qa[i].x * kb[j].x + qa[i].y * kb[j].y
                             + qa[i].z * kb[j].z + qa[i].w * kb[j].w;
        }

        // online softmax update
#pragma unroll
        for (int i = 0; i < 4; i++) {
            float s0 = s[i][0] * 0.125f, s1 = s[i][1] * 0.125f;
            float s2 = s[i][2] * 0.125f, s3 = s[i][3] * 0.125f;
            float ml = fmaxf(fmaxf(s0, s1), fmaxf(s2, s3));
#pragma unroll
            for (int off = 8; off; off >>= 1)
                ml = fmaxf(ml, __shfl_xor_sync(0xffffffffu, ml, off));
            float mnew = fmaxf(m[i], ml);
            float alpha = __expf(m[i] - mnew);
            float4 p4;
            p4.x = __expf(s0 - mnew);
            p4.y = __expf(s1 - mnew);
            p4.z = __expf(s2 - mnew);
            p4.w = __expf(s3 - mnew);
            float psum = p4.x + p4.y + p4.z + p4.w;
#pragma unroll
            for (int off = 8; off; off >>= 1)
                psum += __shfl_xor_sync(0xffffffffu, psum, off);
            l[i] = l[i] * alpha + psum;
            m[i] = mnew;
#pragma unroll
            for (int j = 0; j < 4; j++) o[i][j] *= alpha;
            *(float4*)&Ps[(ty * 4 + i) * APITCH + tx * 4] = p4;
        }

        __syncthreads();                      // Ps visible, K reads done
        att_load_tile(KVs, Vbase, kt * 64);   // overwrite with V
        __syncthreads();

        // O += P V
#pragma unroll
        for (int kk4 = 0; kk4 < 16; kk4++) {
            float pr[4][4];
#pragma unroll
            for (int i = 0; i < 4; i++)
                *(float4*)&pr[i][0] =
                    *(const float4*)&Ps[(ty * 4 + i) * APITCH + kk4 * 4];
#pragma unroll
            for (int c = 0; c < 4; c++) {
                float4 vv = *(const float4*)&KVs[(kk4 * 4 + c) * APITCH + tx * 4];
#pragma unroll
                for (int i = 0; i < 4; i++) {
                    float pv = pr[i][c];
                    o[i][0] += pv * vv.x;
                    o[i][1] += pv * vv.y;
                    o[i][2] += pv * vv.z;
                    o[i][3] += pv * vv.w;
                }
            }
        }
    }

    // epilogue: normalize and write ctx in [B,S,H*DV]
#pragma unroll
    for (int i = 0; i < 4; i++) {
        float inv = 1.f / l[i];
        float4 out;
        out.x = o[i][0] * inv; out.y = o[i][1] * inv;
        out.z = o[i][2] * inv; out.w = o[i][3] * inv;
        const size_t addr = (size_t)(b * SS + q0 + ty * 4 + i) * DD
                          + (size_t)h * 64 + tx * 4;
        *(float4*)(CTX + addr) = out;
    }
}

// ----------------------------------------------------------------------------
// LayerNorm: one block per row (1024 elems, 256 threads x float4)
// ----------------------------------------------------------------------------
__global__ __launch_bounds__(256) void ln_kernel(
    const float* __restrict__ X, const float* __restrict__ gamma,
    const float* __restrict__ beta, float* __restrict__ out)
{
    __shared__ float sh[18];
    const int row = blockIdx.x;
    const int tid = threadIdx.x;
    const float* xr = X + (size_t)row * DD;
    float4 v = *(const float4*)(xr + tid * 4);
    float s  = v.x + v.y + v.z + v.w;
    float sq = v.x * v.x + v.y * v.y + v.z * v.z + v.w * v.w;
#pragma unroll
    for (int off = 16; off; off >>= 1) {
        s  += __shfl_xor_sync(0xffffffffu, s, off);
        sq += __shfl_xor_sync(0xffffffffu, sq, off);
    }
    const int warp = tid >> 5;
    if ((tid & 31) == 0) { sh[warp] = s; sh[8 + warp] = sq; }
    __syncthreads();
    if (tid == 0) {
        float ts = 0.f, tq = 0.f;
#pragma unroll
        for (int w = 0; w < 8; w++) { ts += sh[w]; tq += sh[8 + w]; }
        float mu = ts * (1.f / DD);
        float var = tq * (1.f / DD) - mu * mu;
        sh[16] = mu;
        sh[17] = rsqrtf(var + 1e-5f);
    }
    __syncthreads();
    const float mu = sh[16], rstd = sh[17];
    float4 g = *(const float4*)(gamma + tid * 4);
    float4 bt = *(const float4*)(beta + tid * 4);
    float4 o;
    o.x = (v.x - mu) * rstd * g.x + bt.x;
    o.y = (v.y - mu) * rstd * g.y + bt.y;
    o.z = (v.z - mu) * rstd * g.z + bt.z;
    o.w = (v.w - mu) * rstd * g.w + bt.w;
    *(float4*)(out + (size_t)row * DD + tid * 4) = o;
}

// ----------------------------------------------------------------------------
// Launch
// ----------------------------------------------------------------------------
extern "C" void kernel_launch(void* const* d_in, const int* in_sizes, int n_in,
                              void* d_out, int out_size)
{
    const float* q     = (const float*)d_in[0];
    const float* k     = (const float*)d_in[1];
    const float* v     = (const float*)d_in[2];
    const float* Wq    = (const float*)d_in[3];
    const float* bq    = (const float*)d_in[4];
    const float* Wk    = (const float*)d_in[5];
    const float* bk    = (const float*)d_in[6];
    const float* Wv    = (const float*)d_in[7];
    const float* bv    = (const float*)d_in[8];
    const float* Wfc   = (const float*)d_in[9];
    const float* bfc   = (const float*)d_in[10];
    const float* gamma = (const float*)d_in[11];
    const float* beta  = (const float*)d_in[12];
    float* out = (float*)d_out;

    float *qp, *kp, *vp, *ctx, *xres;
    cudaGetSymbolAddress((void**)&qp,   g_qp);
    cudaGetSymbolAddress((void**)&kp,   g_kp);
    cudaGetSymbolAddress((void**)&vp,   g_vp);
    cudaGetSymbolAddress((void**)&ctx,  g_ctx);
    cudaGetSymbolAddress((void**)&xres, g_x);

    dim3 gg(DD / 128, BS / 128);   // (8, 64)

    sgemm128<<<gg, 256>>>(q, Wq, bq, nullptr, qp);
    sgemm128<<<gg, 256>>>(k, Wk, bk, nullptr, kp);
    sgemm128<<<gg, 256>>>(v, Wv, bv, nullptr, vp);

    cudaFuncSetAttribute(attn_kernel,
                         cudaFuncAttributeMaxDynamicSharedMemorySize,
                         ASMEM_BYTES);
    attn_kernel<<<dim3(SS / 64, BB * HH), 256, ASMEM_BYTES>>>(qp, kp, vp, ctx);

    sgemm128<<<gg, 256>>>(ctx, Wfc, bfc, qp, xres);

    ln_kernel<<<BS, 256>>>(xres, gamma, beta, out);
}

// round 3
// speedup vs baseline: 4.3149x; 4.3149x over previous
#include <cuda_runtime.h>
#include <math.h>
#include <stdint.h>

// ----------------------------------------------------------------------------
// Problem constants
// ----------------------------------------------------------------------------
#define BB 4
#define SS 2048
#define DD 1024
#define HH 16
#define BS (BB * SS)            // 8192 rows
#define NELEM (BS * DD)         // 8388608

// ----------------------------------------------------------------------------
// Device scratch
// ----------------------------------------------------------------------------
__device__ float g_qp[NELEM];       // Q projection (tf32-rounded) + residual
__device__ float g_kp[NELEM];
__device__ float g_vp[NELEM];
__device__ float g_ctx[NELEM];      // attention context (tf32-rounded)
__device__ float g_x[NELEM];        // fc out + residual (full fp32)
__device__ float g_tq[NELEM];       // tf32-rounded inputs
__device__ float g_tk[NELEM];
__device__ float g_tv[NELEM];
__device__ float g_wq[DD * DD];     // tf32-rounded weights
__device__ float g_wk[DD * DD];
__device__ float g_wv[DD * DD];
__device__ float g_wfc[DD * DD];

// ----------------------------------------------------------------------------
// Helpers
// ----------------------------------------------------------------------------
__device__ __forceinline__ float tf32_rna(float x) {
    float r;
    asm("cvt.rna.tf32.f32 %0, %1;" : "=f"(r) : "f"(x));
    return r;
}
__device__ __forceinline__ unsigned fbits(float x) { return __float_as_uint(x); }

__device__ __forceinline__ void cpa16(void* dst, const void* src) {
    unsigned d = (unsigned)__cvta_generic_to_shared(dst);
    asm volatile("cp.async.cg.shared.global [%0], [%1], 16;\n" :: "r"(d), "l"(src));
}
__device__ __forceinline__ void cpa_commit() {
    asm volatile("cp.async.commit_group;\n");
}
__device__ __forceinline__ void cpa_wait1() {
    asm volatile("cp.async.wait_group 1;\n");
}

// mma.sync m16n8k8 tf32, fp32 accum, D += A*B
__device__ __forceinline__ void mma_tf32(float* d, const unsigned* a, const unsigned* b) {
    asm volatile(
        "mma.sync.aligned.m16n8k8.row.col.f32.tf32.tf32.f32 "
        "{%0,%1,%2,%3}, {%4,%5,%6,%7}, {%8,%9}, {%0,%1,%2,%3};\n"
        : "+f"(d[0]), "+f"(d[1]), "+f"(d[2]), "+f"(d[3])
        : "r"(a[0]), "r"(a[1]), "r"(a[2]), "r"(a[3]), "r"(b[0]), "r"(b[1]));
}

// ----------------------------------------------------------------------------
// tf32 RN conversion pass
// ----------------------------------------------------------------------------
__global__ __launch_bounds__(256) void cvt_tf32_kernel(
    const float* __restrict__ in, float* __restrict__ out, int n4)
{
    int i = blockIdx.x * blockDim.x + threadIdx.x;
    if (i < n4) {
        float4 v = ((const float4*)in)[i];
        v.x = tf32_rna(v.x); v.y = tf32_rna(v.y);
        v.z = tf32_rna(v.z); v.w = tf32_rna(v.w);
        ((float4*)out)[i] = v;
    }
}

// ----------------------------------------------------------------------------
// tf32 tensor-core GEMM: C[8192,1024] = A @ W + bias (+res), optional tf32 round
// 128x128x16 tile, 3-stage cp.async, 8 warps (4x1 m, 2 n), warp tile 32x64
// ----------------------------------------------------------------------------
#define G_APITCH 20
#define G_BPITCH 136
#define G_ASTG (128 * G_APITCH)      // 2560 floats/stage
#define G_BSTG (16 * G_BPITCH)       // 2176 floats/stage
#define G_SMEM_FLOATS (3 * (G_ASTG + G_BSTG))
#define G_SMEM_BYTES (G_SMEM_FLOATS * 4)

__global__ __launch_bounds__(256) void gemm_tc(
    const float* __restrict__ A, const float* __restrict__ W,
    const float* __restrict__ bias, const float* __restrict__ res,
    float* __restrict__ C, int doRound)
{
    extern __shared__ float sm[];
    float* AsBase = sm;
    float* BsBase = sm + 3 * G_ASTG;

    const int tid  = threadIdx.x;
    const int lane = tid & 31;
    const int wid  = tid >> 5;
    const int wm   = wid & 3;        // 0..3 -> 32-row strip
    const int wn   = wid >> 2;       // 0..1 -> 64-col strip
    const int row0 = blockIdx.y * 128;
    const int col0 = blockIdx.x * 128;
    const int lq   = lane >> 2;      // 0..7
    const int lr   = lane & 3;       // 0..3

    float acc[2][8][4];
#pragma unroll
    for (int mt = 0; mt < 2; mt++)
#pragma unroll
        for (int nt = 0; nt < 8; nt++)
#pragma unroll
            for (int c = 0; c < 4; c++) acc[mt][nt][c] = 0.f;

    // stage loader: A tile 128x16 (transposed into [m][k] pitch 20),
    //               B tile 16x128 ([k][n] pitch 136)
    auto load_stage = [&](int s, int kt) {
        float* As = AsBase + s * G_ASTG;
        float* Bs = BsBase + s * G_BSTG;
#pragma unroll
        for (int j = 0; j < 2; j++) {
            int c = tid + 256 * j;           // 0..511
            int ar = c >> 2, akc = c & 3;    // row 0..127, kchunk 0..3
            cpa16(As + ar * G_APITCH + akc * 4,
                  A + (size_t)(row0 + ar) * DD + kt * 16 + akc * 4);
            int br = c >> 5, bnc = c & 31;   // k 0..15, nchunk 0..31
            cpa16(Bs + br * G_BPITCH + bnc * 4,
                  W + (size_t)(kt * 16 + br) * DD + col0 + bnc * 4);
        }
    };

    const int NT = DD / 16;   // 64
    load_stage(0, 0); cpa_commit();
    load_stage(1, 1); cpa_commit();

    for (int it = 0; it < NT; it++) {
        cpa_wait1();
        __syncthreads();
        if (it + 2 < NT) load_stage((it + 2) % 3, it + 2);
        cpa_commit();

        const float* Ac = AsBase + (it % 3) * G_ASTG;
        const float* Bc = BsBase + (it % 3) * G_BSTG;
#pragma unroll
        for (int ks = 0; ks < 2; ks++) {
            const int k0 = ks * 8;
            unsigned a[2][4];
#pragma unroll
            for (int mt = 0; mt < 2; mt++) {
                const float* ap = Ac + (wm * 32 + mt * 16 + lq) * G_APITCH + k0 + lr;
                a[mt][0] = fbits(ap[0]);
                a[mt][1] = fbits(ap[8 * G_APITCH]);
                a[mt][2] = fbits(ap[4]);
                a[mt][3] = fbits(ap[8 * G_APITCH + 4]);
            }
            unsigned b[8][2];
#pragma unroll
            for (int nt = 0; nt < 8; nt++) {
                const float* bp = Bc + (k0 + lr) * G_BPITCH + wn * 64 + nt * 8 + lq;
                b[nt][0] = fbits(bp[0]);
                b[nt][1] = fbits(bp[4 * G_BPITCH]);
            }
#pragma unroll
            for (int mt = 0; mt < 2; mt++)
#pragma unroll
                for (int nt = 0; nt < 8; nt++)
                    mma_tf32(acc[mt][nt], a[mt], b[nt]);
        }
    }

    // epilogue
#pragma unroll
    for (int mt = 0; mt < 2; mt++) {
#pragma unroll
        for (int nt = 0; nt < 8; nt++) {
            const int r  = row0 + wm * 32 + mt * 16 + lq;
            const int cb = col0 + wn * 64 + nt * 8 + 2 * lr;
            const float b0 = bias[cb], b1 = bias[cb + 1];
            float v00 = acc[mt][nt][0] + b0, v01 = acc[mt][nt][1] + b1;
            float v10 = acc[mt][nt][2] + b0, v11 = acc[mt][nt][3] + b1;
            if (res) {
                const float* rr0 = res + (size_t)r * DD + cb;
                const float* rr1 = res + (size_t)(r + 8) * DD + cb;
                v00 += rr0[0]; v01 += rr0[1];
                v10 += rr1[0]; v11 += rr1[1];
            }
            if (doRound) {
                v00 = tf32_rna(v00); v01 = tf32_rna(v01);
                v10 = tf32_rna(v10); v11 = tf32_rna(v11);
            }
            *(float2*)(C + (size_t)r * DD + cb)       = make_float2(v00, v01);
            *(float2*)(C + (size_t)(r + 8) * DD + cb) = make_float2(v10, v11);
        }
    }
}

// ----------------------------------------------------------------------------
// Flash attention, tf32 tensor cores.
// Block = (b*H+h, 64-row q tile), 128 threads (4 warps, 16 q-rows each).
// Q frags resident in registers; K/V double-buffered cp.async; P via smem.
// ----------------------------------------------------------------------------
#define A_KPITCH 68
#define A_VPITCH 72
#define A_PPITCH 68
#define A_KSTG (64 * A_KPITCH)
#define A_VSTG (64 * A_VPITCH)
#define A_SMEM_FLOATS (2 * A_KSTG + 2 * A_VSTG + 64 * A_PPITCH)
#define A_SMEM_BYTES (A_SMEM_FLOATS * 4)

__global__ __launch_bounds__(128) void attn_tc(
    const float* __restrict__ QP, const float* __restrict__ KP,
    const float* __restrict__ VP, float* __restrict__ CTX)
{
    extern __shared__ float sm[];
    float* KsBase = sm;
    float* VsBase = sm + 2 * A_KSTG;
    float* Ps     = sm + 2 * A_KSTG + 2 * A_VSTG;

    const int tid  = threadIdx.x;
    const int lane = tid & 31;
    const int wid  = tid >> 5;       // 0..3
    const int lq   = lane >> 2;      // 0..7
    const int lr   = lane & 3;       // 0..3
    const int bh   = blockIdx.y;
    const int b    = bh >> 4;
    const int h    = bh & 15;
    const int q0   = blockIdx.x * 64;

    const size_t headoff = (size_t)b * SS * DD + (size_t)h * 64;
    const float* Qb = QP + headoff;
    const float* Kb = KP + headoff;
    const float* Vb = VP + headoff;

    // load Q fragments (scaled by 1/8: exact on tf32 values)
    unsigned qf[8][4];
    {
        const int r = q0 + wid * 16 + lq;
#pragma unroll
        for (int kk = 0; kk < 8; kk++) {
            const float* p = Qb + (size_t)r * DD + kk * 8 + lr;
            qf[kk][0] = fbits(p[0] * 0.125f);
            qf[kk][1] = fbits(p[(size_t)8 * DD] * 0.125f);
            qf[kk][2] = fbits(p[4] * 0.125f);
            qf[kk][3] = fbits(p[(size_t)8 * DD + 4] * 0.125f);
        }
    }

    float o[8][4];
#pragma unroll
    for (int nt = 0; nt < 8; nt++)
#pragma unroll
        for (int c = 0; c < 4; c++) o[nt][c] = 0.f;
    float mrow[2] = {-INFINITY, -INFINITY};
    float lrow[2] = {0.f, 0.f};

    auto load_kv = [&](int s, int kt) {
        float* Ks = KsBase + s * A_KSTG;
        float* Vs = VsBase + s * A_VSTG;
#pragma unroll
        for (int j = 0; j < 8; j++) {
            int c = tid + 128 * j;           // 0..1023
            int r = c >> 4, kc = c & 15;     // row 0..63, chunk 0..15
            const size_t goff = (size_t)(kt * 64 + r) * DD + kc * 4;
            cpa16(Ks + r * A_KPITCH + kc * 4, Kb + goff);
            cpa16(Vs + r * A_VPITCH + kc * 4, Vb + goff);
        }
    };

    const int NT = SS / 64;   // 32
    load_kv(0, 0); cpa_commit();
    load_kv(1, 1); cpa_commit();

    for (int kt = 0; kt < NT; kt++) {
        cpa_wait1();
        __syncthreads();
        const float* Kc = KsBase + (kt & 1) * A_KSTG;
        const float* Vc = VsBase + (kt & 1) * A_VSTG;

        // S = (Q/8) K^T : 16x64 per warp
        float sacc[8][4];
#pragma unroll
        for (int nt = 0; nt < 8; nt++)
#pragma unroll
            for (int c = 0; c < 4; c++) sacc[nt][c] = 0.f;
#pragma unroll
        for (int kk = 0; kk < 8; kk++) {
#pragma unroll
            for (int nt = 0; nt < 8; nt++) {
                const float* bp = Kc + (nt * 8 + lq) * A_KPITCH + kk * 8 + lr;
                unsigned bf[2] = { fbits(bp[0]), fbits(bp[4]) };
                mma_tf32(sacc[nt], qf[kk], bf);
            }
        }

        // online softmax (frag layout: c0,c1 -> row lq ; c2,c3 -> row lq+8)
#pragma unroll
        for (int r = 0; r < 2; r++) {
            float mx = -INFINITY;
#pragma unroll
            for (int nt = 0; nt < 8; nt++)
                mx = fmaxf(mx, fmaxf(sacc[nt][2 * r], sacc[nt][2 * r + 1]));
            mx = fmaxf(mx, __shfl_xor_sync(0xffffffffu, mx, 1));
            mx = fmaxf(mx, __shfl_xor_sync(0xffffffffu, mx, 2));
            float mnew  = fmaxf(mrow[r], mx);
            float alpha = __expf(mrow[r] - mnew);
            float ps = 0.f;
#pragma unroll
            for (int nt = 0; nt < 8; nt++) {
                float e0 = __expf(sacc[nt][2 * r] - mnew);
                float e1 = __expf(sacc[nt][2 * r + 1] - mnew);
                ps += e0 + e1;
                sacc[nt][2 * r] = e0; sacc[nt][2 * r + 1] = e1;
            }
            ps += __shfl_xor_sync(0xffffffffu, ps, 1);
            ps += __shfl_xor_sync(0xffffffffu, ps, 2);
            lrow[r] = lrow[r] * alpha + ps;
            mrow[r] = mnew;
#pragma unroll
            for (int nt = 0; nt < 8; nt++) {
                o[nt][2 * r]     *= alpha;
                o[nt][2 * r + 1] *= alpha;
            }
        }

        // store P (tf32-rounded) to smem
        {
            const int pr0 = wid * 16 + lq;
#pragma unroll
            for (int nt = 0; nt < 8; nt++) {
                const int pc = nt * 8 + 2 * lr;
                *(float2*)(Ps + pr0 * A_PPITCH + pc) =
                    make_float2(tf32_rna(sacc[nt][0]), tf32_rna(sacc[nt][1]));
                *(float2*)(Ps + (pr0 + 8) * A_PPITCH + pc) =
                    make_float2(tf32_rna(sacc[nt][2]), tf32_rna(sacc[nt][3]));
            }
        }
        __syncthreads();

        // O += P V
#pragma unroll
        for (int kk = 0; kk < 8; kk++) {
            unsigned pa[4];
            const float* pp = Ps + (wid * 16 + lq) * A_PPITCH + kk * 8 + lr;
            pa[0] = fbits(pp[0]);
            pa[1] = fbits(pp[8 * A_PPITCH]);
            pa[2] = fbits(pp[4]);
            pa[3] = fbits(pp[8 * A_PPITCH + 4]);
#pragma unroll
            for (int nt = 0; nt < 8; nt++) {
                const float* vp = Vc + (kk * 8 + lr) * A_VPITCH + nt * 8 + lq;
                unsigned bf[2] = { fbits(vp[0]), fbits(vp[4 * A_VPITCH]) };
                mma_tf32(o[nt], pa, bf);
            }
        }
        __syncthreads();   // all warps done with Ks/Vs/Ps before refill
        if (kt + 2 < NT) load_kv(kt & 1, kt + 2);
        cpa_commit();
    }

    // epilogue: normalize, round, store ctx in [B,S,H*DV]
    {
        const float inv0 = 1.f / lrow[0];
        const float inv1 = 1.f / lrow[1];
        const int r0 = q0 + wid * 16 + lq;
#pragma unroll
        for (int nt = 0; nt < 8; nt++) {
            const int col = h * 64 + nt * 8 + 2 * lr;
            *(float2*)(CTX + (size_t)(b * SS + r0) * DD + col) =
                make_float2(tf32_rna(o[nt][0] * inv0), tf32_rna(o[nt][1] * inv0));
            *(float2*)(CTX + (size_t)(b * SS + r0 + 8) * DD + col) =
                make_float2(tf32_rna(o[nt][2] * inv1), tf32_rna(o[nt][3] * inv1));
        }
    }
}

// ----------------------------------------------------------------------------
// LayerNorm: one block per row
// ----------------------------------------------------------------------------
__global__ __launch_bounds__(256) void ln_kernel(
    const float* __restrict__ X, const float* __restrict__ gamma,
    const float* __restrict__ beta, float* __restrict__ out)
{
    __shared__ float sh[18];
    const int row = blockIdx.x;
    const int tid = threadIdx.x;
    const float* xr = X + (size_t)row * DD;
    float4 v = *(const float4*)(xr + tid * 4);
    float s  = v.x + v.y + v.z + v.w;
    float sq = v.x * v.x + v.y * v.y + v.z * v.z + v.w * v.w;
#pragma unroll
    for (int off = 16; off; off >>= 1) {
        s  += __shfl_xor_sync(0xffffffffu, s, off);
        sq += __shfl_xor_sync(0xffffffffu, sq, off);
    }
    const int warp = tid >> 5;
    if ((tid & 31) == 0) { sh[warp] = s; sh[8 + warp] = sq; }
    __syncthreads();
    if (tid == 0) {
        float ts = 0.f, tq = 0.f;
#pragma unroll
        for (int w = 0; w < 8; w++) { ts += sh[w]; tq += sh[8 + w]; }
        float mu = ts * (1.f / DD);
        float var = tq * (1.f / DD) - mu * mu;
        sh[16] = mu;
        sh[17] = rsqrtf(var + 1e-5f);
    }
    __syncthreads();
    const float mu = sh[16], rstd = sh[17];
    float4 g = *(const float4*)(gamma + tid * 4);
    float4 bt = *(const float4*)(beta + tid * 4);
    float4 o;
    o.x = (v.x - mu) * rstd * g.x + bt.x;
    o.y = (v.y - mu) * rstd * g.y + bt.y;
    o.z = (v.z - mu) * rstd * g.z + bt.z;
    o.w = (v.w - mu) * rstd * g.w + bt.w;
    *(float4*)(out + (size_t)row * DD + tid * 4) = o;
}

// ----------------------------------------------------------------------------
// Launch
// ----------------------------------------------------------------------------
extern "C" void kernel_launch(void* const* d_in, const int* in_sizes, int n_in,
                              void* d_out, int out_size)
{
    const float* q     = (const float*)d_in[0];
    const float* k     = (const float*)d_in[1];
    const float* v     = (const float*)d_in[2];
    const float* Wq    = (const float*)d_in[3];
    const float* bq    = (const float*)d_in[4];
    const float* Wk    = (const float*)d_in[5];
    const float* bk    = (const float*)d_in[6];
    const float* Wv    = (const float*)d_in[7];
    const float* bv    = (const float*)d_in[8];
    const float* Wfc   = (const float*)d_in[9];
    const float* bfc   = (const float*)d_in[10];
    const float* gamma = (const float*)d_in[11];
    const float* beta  = (const float*)d_in[12];
    float* out = (float*)d_out;

    float *qp, *kp, *vp, *ctx, *xres, *tq, *tk, *tv, *wq, *wk, *wv, *wfc;
    cudaGetSymbolAddress((void**)&qp,   g_qp);
    cudaGetSymbolAddress((void**)&kp,   g_kp);
    cudaGetSymbolAddress((void**)&vp,   g_vp);
    cudaGetSymbolAddress((void**)&ctx,  g_ctx);
    cudaGetSymbolAddress((void**)&xres, g_x);
    cudaGetSymbolAddress((void**)&tq,   g_tq);
    cudaGetSymbolAddress((void**)&tk,   g_tk);
    cudaGetSymbolAddress((void**)&tv,   g_tv);
    cudaGetSymbolAddress((void**)&wq,   g_wq);
    cudaGetSymbolAddress((void**)&wk,   g_wk);
    cudaGetSymbolAddress((void**)&wv,   g_wv);
    cudaGetSymbolAddress((void**)&wfc,  g_wfc);

    cudaFuncSetAttribute(gemm_tc, cudaFuncAttributeMaxDynamicSharedMemorySize,
                         G_SMEM_BYTES);
    cudaFuncSetAttribute(attn_tc, cudaFuncAttributeMaxDynamicSharedMemorySize,
                         A_SMEM_BYTES);

    // tf32 RN pre-rounding of all mma inputs
    const int n4 = NELEM / 4, w4 = (DD * DD) / 4;
    cvt_tf32_kernel<<<(n4 + 255) / 256, 256>>>(q, tq, n4);
    cvt_tf32_kernel<<<(n4 + 255) / 256, 256>>>(k, tk, n4);
    cvt_tf32_kernel<<<(n4 + 255) / 256, 256>>>(v, tv, n4);
    cvt_tf32_kernel<<<(w4 + 255) / 256, 256>>>(Wq, wq, w4);
    cvt_tf32_kernel<<<(w4 + 255) / 256, 256>>>(Wk, wk, w4);
    cvt_tf32_kernel<<<(w4 + 255) / 256, 256>>>(Wv, wv, w4);
    cvt_tf32_kernel<<<(w4 + 255) / 256, 256>>>(Wfc, wfc, w4);

    dim3 gg(DD / 128, BS / 128);   // (8, 64)
    gemm_tc<<<gg, 256, G_SMEM_BYTES>>>(tq, wq, bq, nullptr, qp, 1);
    gemm_tc<<<gg, 256, G_SMEM_BYTES>>>(tk, wk, bk, nullptr, kp, 1);
    gemm_tc<<<gg, 256, G_SMEM_BYTES>>>(tv, wv, bv, nullptr, vp, 1);

    attn_tc<<<dim3(SS / 64, BB * HH), 128, A_SMEM_BYTES>>>(qp, kp, vp, ctx);

    gemm_tc<<<gg, 256, G_SMEM_BYTES>>>(ctx, wfc, bfc, qp, xres, 0);

    ln_kernel<<<BS, 256>>>(xres, gamma, beta, out);
}

// round 4
// speedup vs baseline: 4.8367x; 1.1209x over previous
#include <cuda_runtime.h>
#include <math.h>
#include <stdint.h>

// ----------------------------------------------------------------------------
// Problem constants
// ----------------------------------------------------------------------------
#define BB 4
#define SS 2048
#define DD 1024
#define HH 16
#define BS (BB * SS)            // 8192 rows
#define NELEM (BS * DD)         // 8388608

// ----------------------------------------------------------------------------
// Device scratch
// ----------------------------------------------------------------------------
__device__ float g_qp[NELEM];       // projections (tf32-rounded)
__device__ float g_kp[NELEM];
__device__ float g_vp[NELEM];
__device__ float g_ctx[NELEM];      // attention context (tf32-rounded)
__device__ float g_x[NELEM];        // fc out + residual (full fp32)
__device__ float g_wq[DD * DD];     // tf32-rounded weights
__device__ float g_wk[DD * DD];
__device__ float g_wv[DD * DD];
__device__ float g_wfc[DD * DD];

// ----------------------------------------------------------------------------
// Helpers
// ----------------------------------------------------------------------------
__device__ __forceinline__ float tf32_rna(float x) {
    float r;
    asm("cvt.rna.tf32.f32 %0, %1;" : "=f"(r) : "f"(x));
    return r;
}
__device__ __forceinline__ unsigned fbits(float x) { return __float_as_uint(x); }
__device__ __forceinline__ unsigned fbits_rna(float x) {
    return __float_as_uint(tf32_rna(x));
}

__device__ __forceinline__ void cpa16(void* dst, const void* src) {
    unsigned d = (unsigned)__cvta_generic_to_shared(dst);
    asm volatile("cp.async.cg.shared.global [%0], [%1], 16;\n" :: "r"(d), "l"(src));
}
__device__ __forceinline__ void cpa_commit() {
    asm volatile("cp.async.commit_group;\n");
}
__device__ __forceinline__ void cpa_wait1() {
    asm volatile("cp.async.wait_group 1;\n");
}

// mma.sync m16n8k8 tf32, fp32 accum, D += A*B
__device__ __forceinline__ void mma_tf32(float* d, const unsigned* a, const unsigned* b) {
    asm volatile(
        "mma.sync.aligned.m16n8k8.row.col.f32.tf32.tf32.f32 "
        "{%0,%1,%2,%3}, {%4,%5,%6,%7}, {%8,%9}, {%0,%1,%2,%3};\n"
        : "+f"(d[0]), "+f"(d[1]), "+f"(d[2]), "+f"(d[3])
        : "r"(a[0]), "r"(a[1]), "r"(a[2]), "r"(a[3]), "r"(b[0]), "r"(b[1]));
}

// ----------------------------------------------------------------------------
// Batched tf32 RN conversion (weights): grid.y selects tensor
// ----------------------------------------------------------------------------
struct Ptr4 { const float* in[4]; float* out[4]; };

__global__ __launch_bounds__(256) void cvt_w_kernel(Ptr4 p, int n4)
{
    const float* in = p.in[blockIdx.y];
    float* out      = p.out[blockIdx.y];
    int i = blockIdx.x * blockDim.x + threadIdx.x;
    if (i < n4) {
        float4 v = ((const float4*)in)[i];
        v.x = tf32_rna(v.x); v.y = tf32_rna(v.y);
        v.z = tf32_rna(v.z); v.w = tf32_rna(v.w);
        ((float4*)out)[i] = v;
    }
}

// ----------------------------------------------------------------------------
// tf32 tensor-core GEMM core: C[8192,1024] = A @ W + bias (+res)
// 128x128x16 tile, 3-stage cp.async, 8 warps (4 m x 2 n), warp tile 32x64
// ROUND_A: cvt.rna A-fragments in-register (for raw fp32 A inputs)
// ROUND_OUT: tf32-round outputs; HAS_RES: add residual
// ----------------------------------------------------------------------------
#define G_APITCH 20
#define G_BPITCH 136
#define G_ASTG (128 * G_APITCH)      // 2560 floats/stage
#define G_BSTG (16 * G_BPITCH)       // 2176 floats/stage
#define G_SMEM_FLOATS (3 * (G_ASTG + G_BSTG))
#define G_SMEM_BYTES (G_SMEM_FLOATS * 4)

template <bool ROUND_A, bool ROUND_OUT, bool HAS_RES>
__device__ __forceinline__ void gemm_core(
    const float* __restrict__ A, const float* __restrict__ W,
    const float* __restrict__ bias, const float* __restrict__ res,
    float* __restrict__ C)
{
    extern __shared__ float sm[];
    float* AsBase = sm;
    float* BsBase = sm + 3 * G_ASTG;

    const int tid  = threadIdx.x;
    const int lane = tid & 31;
    const int wid  = tid >> 5;
    const int wm   = wid & 3;
    const int wn   = wid >> 2;
    const int row0 = blockIdx.y * 128;
    const int col0 = blockIdx.x * 128;
    const int lq   = lane >> 2;
    const int lr   = lane & 3;

    float acc[2][8][4];
#pragma unroll
    for (int mt = 0; mt < 2; mt++)
#pragma unroll
        for (int nt = 0; nt < 8; nt++)
#pragma unroll
            for (int c = 0; c < 4; c++) acc[mt][nt][c] = 0.f;

    auto load_stage = [&](int s, int kt) {
        float* As = AsBase + s * G_ASTG;
        float* Bs = BsBase + s * G_BSTG;
#pragma unroll
        for (int j = 0; j < 2; j++) {
            int c = tid + 256 * j;
            int ar = c >> 2, akc = c & 3;
            cpa16(As + ar * G_APITCH + akc * 4,
                  A + (size_t)(row0 + ar) * DD + kt * 16 + akc * 4);
            int br = c >> 5, bnc = c & 31;
            cpa16(Bs + br * G_BPITCH + bnc * 4,
                  W + (size_t)(kt * 16 + br) * DD + col0 + bnc * 4);
        }
    };

    const int NT = DD / 16;   // 64
    load_stage(0, 0); cpa_commit();
    load_stage(1, 1); cpa_commit();

    for (int it = 0; it < NT; it++) {
        cpa_wait1();
        __syncthreads();
        if (it + 2 < NT) load_stage((it + 2) % 3, it + 2);
        cpa_commit();

        const float* Ac = AsBase + (it % 3) * G_ASTG;
        const float* Bc = BsBase + (it % 3) * G_BSTG;
#pragma unroll
        for (int ks = 0; ks < 2; ks++) {
            const int k0 = ks * 8;
            unsigned a[2][4];
#pragma unroll
            for (int mt = 0; mt < 2; mt++) {
                const float* ap = Ac + (wm * 32 + mt * 16 + lq) * G_APITCH + k0 + lr;
                if (ROUND_A) {
                    a[mt][0] = fbits_rna(ap[0]);
                    a[mt][1] = fbits_rna(ap[8 * G_APITCH]);
                    a[mt][2] = fbits_rna(ap[4]);
                    a[mt][3] = fbits_rna(ap[8 * G_APITCH + 4]);
                } else {
                    a[mt][0] = fbits(ap[0]);
                    a[mt][1] = fbits(ap[8 * G_APITCH]);
                    a[mt][2] = fbits(ap[4]);
                    a[mt][3] = fbits(ap[8 * G_APITCH + 4]);
                }
            }
            unsigned b[8][2];
#pragma unroll
            for (int nt = 0; nt < 8; nt++) {
                const float* bp = Bc + (k0 + lr) * G_BPITCH + wn * 64 + nt * 8 + lq;
                b[nt][0] = fbits(bp[0]);
                b[nt][1] = fbits(bp[4 * G_BPITCH]);
            }
#pragma unroll
            for (int mt = 0; mt < 2; mt++)
#pragma unroll
                for (int nt = 0; nt < 8; nt++)
                    mma_tf32(acc[mt][nt], a[mt], b[nt]);
        }
    }

#pragma unroll
    for (int mt = 0; mt < 2; mt++) {
#pragma unroll
        for (int nt = 0; nt < 8; nt++) {
            const int r  = row0 + wm * 32 + mt * 16 + lq;
            const int cb = col0 + wn * 64 + nt * 8 + 2 * lr;
            const float b0 = bias[cb], b1 = bias[cb + 1];
            float v00 = acc[mt][nt][0] + b0, v01 = acc[mt][nt][1] + b1;
            float v10 = acc[mt][nt][2] + b0, v11 = acc[mt][nt][3] + b1;
            if (HAS_RES) {
                const float* rr0 = res + (size_t)r * DD + cb;
                const float* rr1 = res + (size_t)(r + 8) * DD + cb;
                v00 += rr0[0]; v01 += rr0[1];
                v10 += rr1[0]; v11 += rr1[1];
            }
            if (ROUND_OUT) {
                v00 = tf32_rna(v00); v01 = tf32_rna(v01);
                v10 = tf32_rna(v10); v11 = tf32_rna(v11);
            }
            *(float2*)(C + (size_t)r * DD + cb)       = make_float2(v00, v01);
            *(float2*)(C + (size_t)(r + 8) * DD + cb) = make_float2(v10, v11);
        }
    }
}

// QKV batched projection: grid.z = 0/1/2 selects (A, W, bias, C)
struct QkvArgs {
    const float* A[3]; const float* W[3]; const float* bias[3]; float* C[3];
};

__global__ __launch_bounds__(256) void qkv_gemm(QkvArgs ga)
{
    const int z = blockIdx.z;
    gemm_core<true, true, false>(ga.A[z], ga.W[z], ga.bias[z], nullptr, ga.C[z]);
}

__global__ __launch_bounds__(256) void fc_gemm(
    const float* __restrict__ A, const float* __restrict__ W,
    const float* __restrict__ bias, const float* __restrict__ res,
    float* __restrict__ C)
{
    gemm_core<false, false, true>(A, W, bias, res, C);
}

// ----------------------------------------------------------------------------
// Flash attention, tf32 tensor cores.
// Block = (b*H+h, 128-row q tile), 256 threads (8 warps, 16 q-rows each).
// Q frags resident in registers; K/V double-buffered cp.async; P via smem.
// ----------------------------------------------------------------------------
#define A_KPITCH 68
#define A_VPITCH 72
#define A_PPITCH 68
#define A_KSTG (64 * A_KPITCH)
#define A_VSTG (64 * A_VPITCH)
#define A_SMEM_FLOATS (2 * A_KSTG + 2 * A_VSTG + 128 * A_PPITCH)
#define A_SMEM_BYTES (A_SMEM_FLOATS * 4)

__global__ __launch_bounds__(256, 2) void attn_tc(
    const float* __restrict__ QP, const float* __restrict__ KP,
    const float* __restrict__ VP, float* __restrict__ CTX)
{
    extern __shared__ float sm[];
    float* KsBase = sm;
    float* VsBase = sm + 2 * A_KSTG;
    float* Ps     = sm + 2 * A_KSTG + 2 * A_VSTG;

    const int tid  = threadIdx.x;
    const int lane = tid & 31;
    const int wid  = tid >> 5;       // 0..7
    const int lq   = lane >> 2;      // 0..7
    const int lr   = lane & 3;       // 0..3
    const int bh   = blockIdx.y;
    const int b    = bh >> 4;
    const int h    = bh & 15;
    const int q0   = blockIdx.x * 128;

    const size_t headoff = (size_t)b * SS * DD + (size_t)h * 64;
    const float* Qb = QP + headoff;
    const float* Kb = KP + headoff;
    const float* Vb = VP + headoff;

    // Q fragments (scaled by 1/8: exact on tf32 values)
    unsigned qf[8][4];
    {
        const int r = q0 + wid * 16 + lq;
#pragma unroll
        for (int kk = 0; kk < 8; kk++) {
            const float* p = Qb + (size_t)r * DD + kk * 8 + lr;
            qf[kk][0] = fbits(p[0] * 0.125f);
            qf[kk][1] = fbits(p[(size_t)8 * DD] * 0.125f);
            qf[kk][2] = fbits(p[4] * 0.125f);
            qf[kk][3] = fbits(p[(size_t)8 * DD + 4] * 0.125f);
        }
    }

    float o[8][4];
#pragma unroll
    for (int nt = 0; nt < 8; nt++)
#pragma unroll
        for (int c = 0; c < 4; c++) o[nt][c] = 0.f;
    float mrow[2] = {-INFINITY, -INFINITY};
    float lrow[2] = {0.f, 0.f};

    auto load_kv = [&](int s, int kt) {
        float* Ks = KsBase + s * A_KSTG;
        float* Vs = VsBase + s * A_VSTG;
#pragma unroll
        for (int j = 0; j < 4; j++) {
            int c = tid + 256 * j;           // 0..1023
            int r = c >> 4, kc = c & 15;     // row 0..63, chunk 0..15
            const size_t goff = (size_t)(kt * 64 + r) * DD + kc * 4;
            cpa16(Ks + r * A_KPITCH + kc * 4, Kb + goff);
            cpa16(Vs + r * A_VPITCH + kc * 4, Vb + goff);
        }
    };

    const int NT = SS / 64;   // 32
    load_kv(0, 0); cpa_commit();
    load_kv(1, 1); cpa_commit();

    for (int kt = 0; kt < NT; kt++) {
        cpa_wait1();
        __syncthreads();
        const float* Kc = KsBase + (kt & 1) * A_KSTG;
        const float* Vc = VsBase + (kt & 1) * A_VSTG;

        // S = (Q/8) K^T : 16x64 per warp
        float sacc[8][4];
#pragma unroll
        for (int nt = 0; nt < 8; nt++)
#pragma unroll
            for (int c = 0; c < 4; c++) sacc[nt][c] = 0.f;
#pragma unroll
        for (int kk = 0; kk < 8; kk++) {
#pragma unroll
            for (int nt = 0; nt < 8; nt++) {
                const float* bp = Kc + (nt * 8 + lq) * A_KPITCH + kk * 8 + lr;
                unsigned bf[2] = { fbits(bp[0]), fbits(bp[4]) };
                mma_tf32(sacc[nt], qf[kk], bf);
            }
        }

        // online softmax (frag: c0,c1 -> row lq ; c2,c3 -> row lq+8)
#pragma unroll
        for (int r = 0; r < 2; r++) {
            float mx = -INFINITY;
#pragma unroll
            for (int nt = 0; nt < 8; nt++)
                mx = fmaxf(mx, fmaxf(sacc[nt][2 * r], sacc[nt][2 * r + 1]));
            mx = fmaxf(mx, __shfl_xor_sync(0xffffffffu, mx, 1));
            mx = fmaxf(mx, __shfl_xor_sync(0xffffffffu, mx, 2));
            float mnew  = fmaxf(mrow[r], mx);
            float alpha = __expf(mrow[r] - mnew);
            float ps = 0.f;
#pragma unroll
            for (int nt = 0; nt < 8; nt++) {
                float e0 = __expf(sacc[nt][2 * r] - mnew);
                float e1 = __expf(sacc[nt][2 * r + 1] - mnew);
                ps += e0 + e1;
                sacc[nt][2 * r] = e0; sacc[nt][2 * r + 1] = e1;
            }
            ps += __shfl_xor_sync(0xffffffffu, ps, 1);
            ps += __shfl_xor_sync(0xffffffffu, ps, 2);
            lrow[r] = lrow[r] * alpha + ps;
            mrow[r] = mnew;
#pragma unroll
            for (int nt = 0; nt < 8; nt++) {
                o[nt][2 * r]     *= alpha;
                o[nt][2 * r + 1] *= alpha;
            }
        }

        // store P (tf32-rounded) to smem
        {
            const int pr0 = wid * 16 + lq;
#pragma unroll
            for (int nt = 0; nt < 8; nt++) {
                const int pc = nt * 8 + 2 * lr;
                *(float2*)(Ps + pr0 * A_PPITCH + pc) =
                    make_float2(tf32_rna(sacc[nt][0]), tf32_rna(sacc[nt][1]));
                *(float2*)(Ps + (pr0 + 8) * A_PPITCH + pc) =
                    make_float2(tf32_rna(sacc[nt][2]), tf32_rna(sacc[nt][3]));
            }
        }
        __syncthreads();

        // O += P V
#pragma unroll
        for (int kk = 0; kk < 8; kk++) {
            unsigned pa[4];
            const float* pp = Ps + (wid * 16 + lq) * A_PPITCH + kk * 8 + lr;
            pa[0] = fbits(pp[0]);
            pa[1] = fbits(pp[8 * A_PPITCH]);
            pa[2] = fbits(pp[4]);
            pa[3] = fbits(pp[8 * A_PPITCH + 4]);
#pragma unroll
            for (int nt = 0; nt < 8; nt++) {
                const float* vp = Vc + (kk * 8 + lr) * A_VPITCH + nt * 8 + lq;
                unsigned bf[2] = { fbits(vp[0]), fbits(vp[4 * A_VPITCH]) };
                mma_tf32(o[nt], pa, bf);
            }
        }
        __syncthreads();   // all warps done with Ks/Vs/Ps before refill
        if (kt + 2 < NT) load_kv(kt & 1, kt + 2);
        cpa_commit();
    }

    // epilogue: normalize, round, store ctx in [B,S,H*DV]
    {
        const float inv0 = 1.f / lrow[0];
        const float inv1 = 1.f / lrow[1];
        const int r0 = q0 + wid * 16 + lq;
#pragma unroll
        for (int nt = 0; nt < 8; nt++) {
            const int col = h * 64 + nt * 8 + 2 * lr;
            *(float2*)(CTX + (size_t)(b * SS + r0) * DD + col) =
                make_float2(tf32_rna(o[nt][0] * inv0), tf32_rna(o[nt][1] * inv0));
            *(float2*)(CTX + (size_t)(b * SS + r0 + 8) * DD + col) =
                make_float2(tf32_rna(o[nt][2] * inv1), tf32_rna(o[nt][3] * inv1));
        }
    }
}

// ----------------------------------------------------------------------------
// LayerNorm: one block per row
// ----------------------------------------------------------------------------
__global__ __launch_bounds__(256) void ln_kernel(
    const float* __restrict__ X, const float* __restrict__ gamma,
    const float* __restrict__ beta, float* __restrict__ out)
{
    __shared__ float sh[18];
    const int row = blockIdx.x;
    const int tid = threadIdx.x;
    const float* xr = X + (size_t)row * DD;
    float4 v = *(const float4*)(xr + tid * 4);
    float s  = v.x + v.y + v.z + v.w;
    float sq = v.x * v.x + v.y * v.y + v.z * v.z + v.w * v.w;
#pragma unroll
    for (int off = 16; off; off >>= 1) {
        s  += __shfl_xor_sync(0xffffffffu, s, off);
        sq += __shfl_xor_sync(0xffffffffu, sq, off);
    }
    const int warp = tid >> 5;
    if ((tid & 31) == 0) { sh[warp] = s; sh[8 + warp] = sq; }
    __syncthreads();
    if (tid == 0) {
        float ts = 0.f, tq = 0.f;
#pragma unroll
        for (int w = 0; w < 8; w++) { ts += sh[w]; tq += sh[8 + w]; }
        float mu = ts * (1.f / DD);
        float var = tq * (1.f / DD) - mu * mu;
        sh[16] = mu;
        sh[17] = rsqrtf(var + 1e-5f);
    }
    __syncthreads();
    const float mu = sh[16], rstd = sh[17];
    float4 g = *(const float4*)(gamma + tid * 4);
    float4 bt = *(const float4*)(beta + tid * 4);
    float4 o;
    o.x = (v.x - mu) * rstd * g.x + bt.x;
    o.y = (v.y - mu) * rstd * g.y + bt.y;
    o.z = (v.z - mu) * rstd * g.z + bt.z;
    o.w = (v.w - mu) * rstd * g.w + bt.w;
    *(float4*)(out + (size_t)row * DD + tid * 4) = o;
}

// ----------------------------------------------------------------------------
// Launch
// ----------------------------------------------------------------------------
extern "C" void kernel_launch(void* const* d_in, const int* in_sizes, int n_in,
                              void* d_out, int out_size)
{
    const float* q     = (const float*)d_in[0];
    const float* k     = (const float*)d_in[1];
    const float* v     = (const float*)d_in[2];
    const float* Wq    = (const float*)d_in[3];
    const float* bq    = (const float*)d_in[4];
    const float* Wk    = (const float*)d_in[5];
    const float* bk    = (const float*)d_in[6];
    const float* Wv    = (const float*)d_in[7];
    const float* bv    = (const float*)d_in[8];
    const float* Wfc   = (const float*)d_in[9];
    const float* bfc   = (const float*)d_in[10];
    const float* gamma = (const float*)d_in[11];
    const float* beta  = (const float*)d_in[12];
    float* out = (float*)d_out;

    float *qp, *kp, *vp, *ctx, *xres, *wq, *wk, *wv, *wfc;
    cudaGetSymbolAddress((void**)&qp,   g_qp);
    cudaGetSymbolAddress((void**)&kp,   g_kp);
    cudaGetSymbolAddress((void**)&vp,   g_vp);
    cudaGetSymbolAddress((void**)&ctx,  g_ctx);
    cudaGetSymbolAddress((void**)&xres, g_x);
    cudaGetSymbolAddress((void**)&wq,   g_wq);
    cudaGetSymbolAddress((void**)&wk,   g_wk);
    cudaGetSymbolAddress((void**)&wv,   g_wv);
    cudaGetSymbolAddress((void**)&wfc,  g_wfc);

    cudaFuncSetAttribute(qkv_gemm, cudaFuncAttributeMaxDynamicSharedMemorySize,
                         G_SMEM_BYTES);
    cudaFuncSetAttribute(fc_gemm, cudaFuncAttributeMaxDynamicSharedMemorySize,
                         G_SMEM_BYTES);
    cudaFuncSetAttribute(attn_tc, cudaFuncAttributeMaxDynamicSharedMemorySize,
                         A_SMEM_BYTES);

    // one batched tf32 rounding pass for all 4 weight matrices
    Ptr4 pw;
    pw.in[0] = Wq;  pw.out[0] = wq;
    pw.in[1] = Wk;  pw.out[1] = wk;
    pw.in[2] = Wv;  pw.out[2] = wv;
    pw.in[3] = Wfc; pw.out[3] = wfc;
    const int w4 = (DD * DD) / 4;
    cvt_w_kernel<<<dim3((w4 + 255) / 256, 4), 256>>>(pw, w4);

    // batched QKV projections (A-side rounded in-register)
    QkvArgs ga;
    ga.A[0] = q; ga.W[0] = wq; ga.bias[0] = bq; ga.C[0] = qp;
    ga.A[1] = k; ga.W[1] = wk; ga.bias[1] = bk; ga.C[1] = kp;
    ga.A[2] = v; ga.W[2] = wv; ga.bias[2] = bv; ga.C[2] = vp;
    qkv_gemm<<<dim3(DD / 128, BS / 128, 3), 256, G_SMEM_BYTES>>>(ga);

    attn_tc<<<dim3(SS / 128, BB * HH), 256, A_SMEM_BYTES>>>(qp, kp, vp, ctx);

    fc_gemm<<<dim3(DD / 128, BS / 128), 256, G_SMEM_BYTES>>>(ctx, wfc, bfc, qp, xres);

    ln_kernel<<<BS, 256>>>(xres, gamma, beta, out);
}

// round 6
// speedup vs baseline: 7.6343x; 1.5784x over previous
#include <cuda_runtime.h>
#include <cuda_fp16.h>
#include <math.h>
#include <stdint.h>

// ----------------------------------------------------------------------------
// Problem constants
// ----------------------------------------------------------------------------
#define BB 4
#define SS 2048
#define DD 1024
#define HH 16
#define BS (BB * SS)            // 8192 rows
#define NELEM (BS * DD)         // 8388608

// ----------------------------------------------------------------------------
// Device scratch
// ----------------------------------------------------------------------------
__device__ __half g_q16[NELEM];     // fp16 inputs
__device__ __half g_k16[NELEM];
__device__ __half g_v16[NELEM];
__device__ __half g_qp16[NELEM];    // Q projection, pre-scaled by 1/8
__device__ __half g_kp16[NELEM];
__device__ __half g_vp16[NELEM];
__device__ __half g_vpt[NELEM];     // V projection transposed: [(b,h,dv)][s]
__device__ __half g_ctx16[NELEM];   // attention context
__device__ float  g_qp32[NELEM];    // fp32 residual copy of Q projection
__device__ float  g_x[NELEM];       // fc out + residual (pre-LN)
__device__ __half g_wq[DD * DD];    // fp16 TRANSPOSED weights [n][k]
__device__ __half g_wk[DD * DD];
__device__ __half g_wv[DD * DD];
__device__ __half g_wfc[DD * DD];

// ----------------------------------------------------------------------------
// Helpers
// ----------------------------------------------------------------------------
__device__ __forceinline__ void cpa16(void* dst, const void* src) {
    unsigned d = (unsigned)__cvta_generic_to_shared(dst);
    asm volatile("cp.async.cg.shared.global [%0], [%1], 16;\n" :: "r"(d), "l"(src));
}
__device__ __forceinline__ void cpa_commit() {
    asm volatile("cp.async.commit_group;\n");
}
__device__ __forceinline__ void cpa_wait1() {
    asm volatile("cp.async.wait_group 1;\n");
}
__device__ __forceinline__ unsigned ldu32(const __half* p) {
    return *(const unsigned*)p;
}

// mma.sync m16n8k16 fp16 -> fp32 accum, D += A*B
__device__ __forceinline__ void mma16(float* d, const unsigned* a, const unsigned* b) {
    asm volatile(
        "mma.sync.aligned.m16n8k16.row.col.f32.f16.f16.f32 "
        "{%0,%1,%2,%3}, {%4,%5,%6,%7}, {%8,%9}, {%0,%1,%2,%3};\n"
        : "+f"(d[0]), "+f"(d[1]), "+f"(d[2]), "+f"(d[3])
        : "r"(a[0]), "r"(a[1]), "r"(a[2]), "r"(a[3]), "r"(b[0]), "r"(b[1]));
}

// ----------------------------------------------------------------------------
// Input conversion: fp32 -> fp16, batched over q/k/v (grid.y)
// ----------------------------------------------------------------------------
struct CvtIn { const float* in[3]; __half* out[3]; };

__global__ __launch_bounds__(256) void cvt_in_kernel(CvtIn p, int n4)
{
    const float* in = p.in[blockIdx.y];
    __half* out     = p.out[blockIdx.y];
    int i = blockIdx.x * blockDim.x + threadIdx.x;
    if (i < n4) {
        float4 v = ((const float4*)in)[i];
        __half2 h2[2];
        h2[0] = __floats2half2_rn(v.x, v.y);
        h2[1] = __floats2half2_rn(v.z, v.w);
        ((uint2*)out)[i] = *(uint2*)h2;
    }
}

// ----------------------------------------------------------------------------
// Weight conversion: fp32 [k][n] -> fp16 TRANSPOSED [n][k], batched (grid.z)
// ----------------------------------------------------------------------------
struct CvtW { const float* in[4]; __half* out[4]; };

__global__ __launch_bounds__(256) void cvt_wt_kernel(CvtW p)
{
    const float* W = p.in[blockIdx.z];
    __half* Wt     = p.out[blockIdx.z];
    __shared__ float tile[32][33];
    const int n0 = blockIdx.x * 32, k0 = blockIdx.y * 32;
    const int tx = threadIdx.x & 31, ty4 = (threadIdx.x >> 5) * 4;
#pragma unroll
    for (int i = 0; i < 4; i++)
        tile[ty4 + i][tx] = W[(size_t)(k0 + ty4 + i) * DD + n0 + tx];
    __syncthreads();
#pragma unroll
    for (int i = 0; i < 4; i++)
        Wt[(size_t)(n0 + ty4 + i) * DD + k0 + tx] = __float2half_rn(tile[tx][ty4 + i]);
}

// ----------------------------------------------------------------------------
// V transpose: vp16 [b*S+s][h*64+dv] -> vpt [(b*16+h)*64+dv][s]
// One block per (64-s tile, b*h). 64x64 fp16 tile through smem.
// ----------------------------------------------------------------------------
__global__ __launch_bounds__(256) void vtrans_kernel(
    const __half* __restrict__ vp, __half* __restrict__ vpt)
{
    __shared__ __half t[64][72];
    const int tid = threadIdx.x;
    const int s0  = blockIdx.x * 64;
    const int bh  = blockIdx.y;
    const int b   = bh >> 4, h = bh & 15;
#pragma unroll
    for (int j = 0; j < 2; j++) {
        int c = tid + 256 * j;            // 0..511
        int r = c >> 3, kc = c & 7;
        *(uint4*)&t[r][kc * 8] =
            *(const uint4*)(vp + (size_t)(b * SS + s0 + r) * DD + h * 64 + kc * 8);
    }
    __syncthreads();
#pragma unroll
    for (int j = 0; j < 2; j++) {
        int c = tid + 256 * j;
        int dv = c >> 3, kc = c & 7;
        __half tmp[8];
#pragma unroll
        for (int i = 0; i < 8; i++) tmp[i] = t[kc * 8 + i][dv];
        *(uint4*)(vpt + (size_t)(bh * 64 + dv) * SS + s0 + kc * 8) = *(uint4*)tmp;
    }
}

// ----------------------------------------------------------------------------
// fp16 tensor-core GEMM core: acc = A[128 rows][1024] @ Wt[128 cols][1024]^T
// 128x128x32 tile, 3-stage cp.async, 8 warps (4 m x 2 n), warp tile 32x64
// A [m][k] and Wt [n][k] both k-contiguous fp16 -> all frag loads are half2.
// ----------------------------------------------------------------------------
#define GP 40                      // smem pitch in halves (32 + 8 pad)
#define GSTG (128 * GP)            // halves per tensor per stage
#define G_SMEM_BYTES (3 * 2 * GSTG * 2)

__device__ __forceinline__ void gemm16_core(
    const __half* __restrict__ A, const __half* __restrict__ Wt,
    float acc[2][8][4])
{
    extern __shared__ __half hsm[];
    __half* As = hsm;
    __half* Bs = hsm + 3 * GSTG;

    const int tid  = threadIdx.x;
    const int lane = tid & 31;
    const int wid  = tid >> 5;
    const int wm   = wid & 3;
    const int wn   = wid >> 2;
    const int row0 = blockIdx.y * 128;
    const int col0 = blockIdx.x * 128;
    const int lq   = lane >> 2;
    const int lr   = lane & 3;

#pragma unroll
    for (int mt = 0; mt < 2; mt++)
#pragma unroll
        for (int nt = 0; nt < 8; nt++)
#pragma unroll
            for (int c = 0; c < 4; c++) acc[mt][nt][c] = 0.f;

    auto load_stage = [&](int s, int kt) {
        __half* Ap = As + s * GSTG;
        __half* Bp = Bs + s * GSTG;
#pragma unroll
        for (int j = 0; j < 2; j++) {
            int c = tid + 256 * j;        // 0..511
            int r = c >> 2, kc = c & 3;
            cpa16(Ap + r * GP + kc * 8, A  + (size_t)(row0 + r) * DD + kt * 32 + kc * 8);
            cpa16(Bp + r * GP + kc * 8, Wt + (size_t)(col0 + r) * DD + kt * 32 + kc * 8);
        }
    };

    const int NT = DD / 32;   // 32
    load_stage(0, 0); cpa_commit();
    load_stage(1, 1); cpa_commit();

    for (int it = 0; it < NT; it++) {
        cpa_wait1();
        __syncthreads();
        if (it + 2 < NT) load_stage((it + 2) % 3, it + 2);
        cpa_commit();

        const __half* Ac = As + (it % 3) * GSTG;
        const __half* Bc = Bs + (it % 3) * GSTG;
#pragma unroll
        for (int ks = 0; ks < 2; ks++) {
            const int k0 = ks * 16;
            unsigned a[2][4];
#pragma unroll
            for (int mt = 0; mt < 2; mt++) {
                const __half* ap = Ac + (wm * 32 + mt * 16 + lq) * GP + k0 + 2 * lr;
                a[mt][0] = ldu32(ap);
                a[mt][1] = ldu32(ap + 8 * GP);
                a[mt][2] = ldu32(ap + 8);
                a[mt][3] = ldu32(ap + 8 * GP + 8);
            }
            unsigned b[8][2];
#pragma unroll
            for (int nt = 0; nt < 8; nt++) {
                const __half* bp = Bc + (wn * 64 + nt * 8 + lq) * GP + k0 + 2 * lr;
                b[nt][0] = ldu32(bp);
                b[nt][1] = ldu32(bp + 8);
            }
#pragma unroll
            for (int mt = 0; mt < 2; mt++)
#pragma unroll
                for (int nt = 0; nt < 8; nt++)
                    mma16(acc[mt][nt], a[mt], b[nt]);
        }
    }
}

// QKV batched projection: grid.z selects (A, Wt, bias, out16); z==0 also
// writes an fp32 residual copy and pre-scales the fp16 output by 1/8.
struct QkvArgs {
    const __half* A[3]; const __half* W[3]; const float* bias[3];
    __half* C16[3]; float* C32;
};

__global__ __launch_bounds__(256, 2) void qkv_gemm(QkvArgs ga)
{
    const int z = blockIdx.z;
    float acc[2][8][4];
    gemm16_core(ga.A[z], ga.W[z], acc);

    const int lane = threadIdx.x & 31;
    const int wid  = threadIdx.x >> 5;
    const int wm   = wid & 3, wn = wid >> 2;
    const int lq   = lane >> 2, lr = lane & 3;
    const int row0 = blockIdx.y * 128, col0 = blockIdx.x * 128;
    const float scale = (z == 0) ? 0.125f : 1.0f;
    const float* bias = ga.bias[z];
    __half* C16 = ga.C16[z];

#pragma unroll
    for (int mt = 0; mt < 2; mt++) {
#pragma unroll
        for (int nt = 0; nt < 8; nt++) {
            const int r  = row0 + wm * 32 + mt * 16 + lq;
            const int cb = col0 + wn * 64 + nt * 8 + 2 * lr;
            const float b0 = bias[cb], b1 = bias[cb + 1];
            float v00 = acc[mt][nt][0] + b0, v01 = acc[mt][nt][1] + b1;
            float v10 = acc[mt][nt][2] + b0, v11 = acc[mt][nt][3] + b1;
            *(__half2*)(C16 + (size_t)r * DD + cb) =
                __floats2half2_rn(v00 * scale, v01 * scale);
            *(__half2*)(C16 + (size_t)(r + 8) * DD + cb) =
                __floats2half2_rn(v10 * scale, v11 * scale);
            if (z == 0) {
                *(float2*)(ga.C32 + (size_t)r * DD + cb)       = make_float2(v00, v01);
                *(float2*)(ga.C32 + (size_t)(r + 8) * DD + cb) = make_float2(v10, v11);
            }
        }
    }
}

__global__ __launch_bounds__(256, 2) void fc_gemm(
    const __half* __restrict__ A, const __half* __restrict__ Wt,
    const float* __restrict__ bias, const float* __restrict__ res,
    float* __restrict__ C)
{
    float acc[2][8][4];
    gemm16_core(A, Wt, acc);

    const int lane = threadIdx.x & 31;
    const int wid  = threadIdx.x >> 5;
    const int wm   = wid & 3, wn = wid >> 2;
    const int lq   = lane >> 2, lr = lane & 3;
    const int row0 = blockIdx.y * 128, col0 = blockIdx.x * 128;

#pragma unroll
    for (int mt = 0; mt < 2; mt++) {
#pragma unroll
        for (int nt = 0; nt < 8; nt++) {
            const int r  = row0 + wm * 32 + mt * 16 + lq;
            const int cb = col0 + wn * 64 + nt * 8 + 2 * lr;
            const float b0 = bias[cb], b1 = bias[cb + 1];
            const float2 r0 = *(const float2*)(res + (size_t)r * DD + cb);
            const float2 r1 = *(const float2*)(res + (size_t)(r + 8) * DD + cb);
            *(float2*)(C + (size_t)r * DD + cb) =
                make_float2(acc[mt][nt][0] + b0 + r0.x, acc[mt][nt][1] + b1 + r0.y);
            *(float2*)(C + (size_t)(r + 8) * DD + cb) =
                make_float2(acc[mt][nt][2] + b0 + r1.x, acc[mt][nt][3] + b1 + r1.y);
        }
    }
}

// ----------------------------------------------------------------------------
// Flash attention, fp16 tensor cores.
// Block = (b*H+h, 128-row q tile), 256 threads (8 warps, 16 q-rows each).
// Q frags in registers (pre-scaled); K and V^T double-buffered cp.async.
// ----------------------------------------------------------------------------
#define AP 72
#define A_KSTG (64 * AP)
#define A_SMEM_HALVES (4 * A_KSTG + 128 * AP)
#define A_SMEM_BYTES (A_SMEM_HALVES * 2)

__global__ __launch_bounds__(256, 2) void attn_tc(
    const __half* __restrict__ QP, const __half* __restrict__ KP,
    const __half* __restrict__ VPT, __half* __restrict__ CTX)
{
    extern __shared__ __half asm16[];
    __half* KsBase = asm16;
    __half* VsBase = asm16 + 2 * A_KSTG;
    __half* Ps     = asm16 + 4 * A_KSTG;

    const int tid  = threadIdx.x;
    const int lane = tid & 31;
    const int wid  = tid >> 5;       // 0..7
    const int lq   = lane >> 2;      // 0..7
    const int lr   = lane & 3;       // 0..3
    const int bh   = blockIdx.y;
    const int b    = bh >> 4;
    const int h    = bh & 15;
    const int q0   = blockIdx.x * 128;

    const __half* Kb  = KP + (size_t)b * SS * DD + (size_t)h * 64;
    const __half* Vtb = VPT + (size_t)bh * 64 * SS;

    // Q fragments (already scaled by 1/8 in projection epilogue)
    unsigned qf[4][4];
    {
        const int r = q0 + wid * 16 + lq;
        const __half* qptr = QP + (size_t)(b * SS + r) * DD + h * 64;
#pragma unroll
        for (int kk = 0; kk < 4; kk++) {
            const __half* p = qptr + kk * 16 + 2 * lr;
            qf[kk][0] = ldu32(p);
            qf[kk][1] = ldu32(p + (size_t)8 * DD);
            qf[kk][2] = ldu32(p + 8);
            qf[kk][3] = ldu32(p + (size_t)8 * DD + 8);
        }
    }

    float o[8][4];
#pragma unroll
    for (int nt = 0; nt < 8; nt++)
#pragma unroll
        for (int c = 0; c < 4; c++) o[nt][c] = 0.f;
    float mrow[2] = {-INFINITY, -INFINITY};
    float lrow[2] = {0.f, 0.f};

    auto load_kv = [&](int s, int kt) {
        __half* Ks = KsBase + s * A_KSTG;
        __half* Vs = VsBase + s * A_KSTG;
#pragma unroll
        for (int j = 0; j < 2; j++) {
            int c = tid + 256 * j;        // 0..511
            int r = c >> 3, kc = c & 7;
            cpa16(Ks + r * AP + kc * 8, Kb + (size_t)(kt * 64 + r) * DD + kc * 8);
            cpa16(Vs + r * AP + kc * 8, Vtb + (size_t)r * SS + kt * 64 + kc * 8);
        }
    };

    const int NT = SS / 64;   // 32
    load_kv(0, 0); cpa_commit();
    load_kv(1, 1); cpa_commit();

    for (int kt = 0; kt < NT; kt++) {
        cpa_wait1();
        __syncthreads();
        const __half* Kc = KsBase + (kt & 1) * A_KSTG;
        const __half* Vc = VsBase + (kt & 1) * A_KSTG;

        // S = (Q/8) K^T : 16x64 per warp
        float sacc[8][4];
#pragma unroll
        for (int nt = 0; nt < 8; nt++)
#pragma unroll
            for (int c = 0; c < 4; c++) sacc[nt][c] = 0.f;
#pragma unroll
        for (int kk = 0; kk < 4; kk++) {
#pragma unroll
            for (int nt = 0; nt < 8; nt++) {
                const __half* bp = Kc + (nt * 8 + lq) * AP + kk * 16 + 2 * lr;
                unsigned bf[2] = { ldu32(bp), ldu32(bp + 8) };
                mma16(sacc[nt], qf[kk], bf);
            }
        }

        // online softmax (frag: c0,c1 -> row lq ; c2,c3 -> row lq+8)
#pragma unroll
        for (int r = 0; r < 2; r++) {
            float mx = -INFINITY;
#pragma unroll
            for (int nt = 0; nt < 8; nt++)
                mx = fmaxf(mx, fmaxf(sacc[nt][2 * r], sacc[nt][2 * r + 1]));
            mx = fmaxf(mx, __shfl_xor_sync(0xffffffffu, mx, 1));
            mx = fmaxf(mx, __shfl_xor_sync(0xffffffffu, mx, 2));
            float mnew  = fmaxf(mrow[r], mx);
            float alpha = __expf(mrow[r] - mnew);
            float ps = 0.f;
#pragma unroll
            for (int nt = 0; nt < 8; nt++) {
                float e0 = __expf(sacc[nt][2 * r] - mnew);
                float e1 = __expf(sacc[nt][2 * r + 1] - mnew);
                ps += e0 + e1;
                sacc[nt][2 * r] = e0; sacc[nt][2 * r + 1] = e1;
            }
            ps += __shfl_xor_sync(0xffffffffu, ps, 1);
            ps += __shfl_xor_sync(0xffffffffu, ps, 2);
            lrow[r] = lrow[r] * alpha + ps;
            mrow[r] = mnew;
#pragma unroll
            for (int nt = 0; nt < 8; nt++) {
                o[nt][2 * r]     *= alpha;
                o[nt][2 * r + 1] *= alpha;
            }
        }

        // store P as fp16 to smem (A-operand layout [m][kv])
        {
            const int pr0 = wid * 16 + lq;
#pragma unroll
            for (int nt = 0; nt < 8; nt++) {
                const int pc = nt * 8 + 2 * lr;
                *(__half2*)(Ps + pr0 * AP + pc) =
                    __floats2half2_rn(sacc[nt][0], sacc[nt][1]);
                *(__half2*)(Ps + (pr0 + 8) * AP + pc) =
                    __floats2half2_rn(sacc[nt][2], sacc[nt][3]);
            }
        }
        __syncthreads();

        // O += P V  (B operand from transposed V tile [dv][kv])
#pragma unroll
        for (int kk = 0; kk < 4; kk++) {
            unsigned pa[4];
            const __half* pp = Ps + (wid * 16 + lq) * AP + kk * 16 + 2 * lr;
            pa[0] = ldu32(pp);
            pa[1] = ldu32(pp + 8 * AP);
            pa[2] = ldu32(pp + 8);
            pa[3] = ldu32(pp + 8 * AP + 8);
#pragma unroll
            for (int nt = 0; nt < 8; nt++) {
                const __half* vb = Vc + (nt * 8 + lq) * AP + kk * 16 + 2 * lr;
                unsigned bf[2] = { ldu32(vb), ldu32(vb + 8) };
                mma16(o[nt], pa, bf);
            }
        }
        __syncthreads();   // all warps done with Ks/Vs/Ps before refill
        if (kt + 2 < NT) load_kv(kt & 1, kt + 2);
        cpa_commit();
    }

    // epilogue: normalize, store ctx fp16 in [B,S,H*DV]
    {
        const float inv0 = 1.f / lrow[0];
        const float inv1 = 1.f / lrow[1];
        const int r0 = q0 + wid * 16 + lq;
#pragma unroll
        for (int nt = 0; nt < 8; nt++) {
            const int col = h * 64 + nt * 8 + 2 * lr;
            *(__half2*)(CTX + (size_t)(b * SS + r0) * DD + col) =
                __floats2half2_rn(o[nt][0] * inv0, o[nt][1] * inv0);
            *(__half2*)(CTX + (size_t)(b * SS + r0 + 8) * DD + col) =
                __floats2half2_rn(o[nt][2] * inv1, o[nt][3] * inv1);
        }
    }
}

// ----------------------------------------------------------------------------
// LayerNorm: one block per row
// ----------------------------------------------------------------------------
__global__ __launch_bounds__(256) void ln_kernel(
    const float* __restrict__ X, const float* __restrict__ gamma,
    const float* __restrict__ beta, float* __restrict__ out)
{
    __shared__ float sh[18];
    const int row = blockIdx.x;
    const int tid = threadIdx.x;
    const float* xr = X + (size_t)row * DD;
    float4 v = *(const float4*)(xr + tid * 4);
    float s  = v.x + v.y + v.z + v.w;
    float sq = v.x * v.x + v.y * v.y + v.z * v.z + v.w * v.w;
#pragma unroll
    for (int off = 16; off; off >>= 1) {
        s  += __shfl_xor_sync(0xffffffffu, s, off);
        sq += __shfl_xor_sync(0xffffffffu, sq, off);
    }
    const int warp = tid >> 5;
    if ((tid & 31) == 0) { sh[warp] = s; sh[8 + warp] = sq; }
    __syncthreads();
    if (tid == 0) {
        float ts = 0.f, tq = 0.f;
#pragma unroll
        for (int w = 0; w < 8; w++) { ts += sh[w]; tq += sh[8 + w]; }
        float mu = ts * (1.f / DD);
        float var = tq * (1.f / DD) - mu * mu;
        sh[16] = mu;
        sh[17] = rsqrtf(var + 1e-5f);
    }
    __syncthreads();
    const float mu = sh[16], rstd = sh[17];
    float4 g = *(const float4*)(gamma + tid * 4);
    float4 bt = *(const float4*)(beta + tid * 4);
    float4 o;
    o.x = (v.x - mu) * rstd * g.x + bt.x;
    o.y = (v.y - mu) * rstd * g.y + bt.y;
    o.z = (v.z - mu) * rstd * g.z + bt.z;
    o.w = (v.w - mu) * rstd * g.w + bt.w;
    *(float4*)(out + (size_t)row * DD + tid * 4) = o;
}

// ----------------------------------------------------------------------------
// Launch
// ----------------------------------------------------------------------------
extern "C" void kernel_launch(void* const* d_in, const int* in_sizes, int n_in,
                              void* d_out, int out_size)
{
    const float* q     = (const float*)d_in[0];
    const float* k     = (const float*)d_in[1];
    const float* v     = (const float*)d_in[2];
    const float* Wq    = (const float*)d_in[3];
    const float* bq    = (const float*)d_in[4];
    const float* Wk    = (const float*)d_in[5];
    const float* bk    = (const float*)d_in[6];
    const float* Wv    = (const float*)d_in[7];
    const float* bv    = (const float*)d_in[8];
    const float* Wfc   = (const float*)d_in[9];
    const float* bfc   = (const float*)d_in[10];
    const float* gamma = (const float*)d_in[11];
    const float* beta  = (const float*)d_in[12];
    float* out = (float*)d_out;

    __half *q16, *k16, *v16, *qp16, *kp16, *vp16, *vpt, *ctx16, *wq, *wk, *wv, *wfc;
    float *qp32, *xres;
    cudaGetSymbolAddress((void**)&q16,   g_q16);
    cudaGetSymbolAddress((void**)&k16,   g_k16);
    cudaGetSymbolAddress((void**)&v16,   g_v16);
    cudaGetSymbolAddress((void**)&qp16,  g_qp16);
    cudaGetSymbolAddress((void**)&kp16,  g_kp16);
    cudaGetSymbolAddress((void**)&vp16,  g_vp16);
    cudaGetSymbolAddress((void**)&vpt,   g_vpt);
    cudaGetSymbolAddress((void**)&ctx16, g_ctx16);
    cudaGetSymbolAddress((void**)&qp32,  g_qp32);
    cudaGetSymbolAddress((void**)&xres,  g_x);
    cudaGetSymbolAddress((void**)&wq,    g_wq);
    cudaGetSymbolAddress((void**)&wk,    g_wk);
    cudaGetSymbolAddress((void**)&wv,    g_wv);
    cudaGetSymbolAddress((void**)&wfc,   g_wfc);

    cudaFuncSetAttribute(qkv_gemm, cudaFuncAttributeMaxDynamicSharedMemorySize,
                         G_SMEM_BYTES);
    cudaFuncSetAttribute(fc_gemm, cudaFuncAttributeMaxDynamicSharedMemorySize,
                         G_SMEM_BYTES);
    cudaFuncSetAttribute(attn_tc, cudaFuncAttributeMaxDynamicSharedMemorySize,
                         A_SMEM_BYTES);

    // fp16 input conversion (batched q/k/v)
    CvtIn ci;
    ci.in[0] = q; ci.out[0] = q16;
    ci.in[1] = k; ci.out[1] = k16;
    ci.in[2] = v; ci.out[2] = v16;
    const int n4 = NELEM / 4;
    cvt_in_kernel<<<dim3(n4 / 256, 3), 256>>>(ci, n4);

    // fp16 transposed weight conversion (batched 4 weights)
    CvtW cw;
    cw.in[0] = Wq;  cw.out[0] = wq;
    cw.in[1] = Wk;  cw.out[1] = wk;
    cw.in[2] = Wv;  cw.out[2] = wv;
    cw.in[3] = Wfc; cw.out[3] = wfc;
    cvt_wt_kernel<<<dim3(DD / 32, DD / 32, 4), 256>>>(cw);

    // batched QKV projections
    QkvArgs ga;
    ga.A[0] = q16; ga.W[0] = wq; ga.bias[0] = bq; ga.C16[0] = qp16;
    ga.A[1] = k16; ga.W[1] = wk; ga.bias[1] = bk; ga.C16[1] = kp16;
    ga.A[2] = v16; ga.W[2] = wv; ga.bias[2] = bv; ga.C16[2] = vp16;
    ga.C32 = qp32;
    qkv_gemm<<<dim3(DD / 128, BS / 128, 3), 256, G_SMEM_BYTES>>>(ga);

    // per-head V transpose for the PV B-operand
    vtrans_kernel<<<dim3(SS / 64, BB * HH), 256>>>(vp16, vpt);

    attn_tc<<<dim3(SS / 128, BB * HH), 256, A_SMEM_BYTES>>>(qp16, kp16, vpt, ctx16);

    fc_gemm<<<dim3(DD / 128, BS / 128), 256, G_SMEM_BYTES>>>(ctx16, wfc, bfc, qp32, xres);

    ln_kernel<<<BS, 256>>>(xres, gamma, beta, out);
}

// round 7
// speedup vs baseline: 8.3382x; 1.0922x over previous
#include <cuda_runtime.h>
#include <cuda_fp16.h>
#include <math.h>
#include <stdint.h>

// ----------------------------------------------------------------------------
// Problem constants
// ----------------------------------------------------------------------------
#define BB 4
#define SS 2048
#define DD 1024
#define HH 16
#define BS (BB * SS)            // 8192 rows
#define NELEM (BS * DD)         // 8388608

// ----------------------------------------------------------------------------
// Device scratch
// ----------------------------------------------------------------------------
__device__ __half g_q16[NELEM];     // fp16 inputs
__device__ __half g_k16[NELEM];
__device__ __half g_v16[NELEM];
__device__ __half g_qp16[NELEM];    // Q projection, pre-scaled by 1/8
__device__ __half g_kp16[NELEM];
__device__ __half g_vp16[NELEM];
__device__ __half g_ctx16[NELEM];   // attention context
__device__ float  g_qp32[NELEM];    // fp32 residual copy of Q projection
__device__ float  g_x[NELEM];       // fc out + residual (pre-LN)
__device__ __half g_wq[DD * DD];    // fp16 TRANSPOSED weights [n][k]
__device__ __half g_wk[DD * DD];
__device__ __half g_wv[DD * DD];
__device__ __half g_wfc[DD * DD];

// ----------------------------------------------------------------------------
// Helpers
// ----------------------------------------------------------------------------
__device__ __forceinline__ void cpa16(void* dst, const void* src) {
    unsigned d = (unsigned)__cvta_generic_to_shared(dst);
    asm volatile("cp.async.cg.shared.global [%0], [%1], 16;\n" :: "r"(d), "l"(src));
}
__device__ __forceinline__ void cpa_commit() {
    asm volatile("cp.async.commit_group;\n");
}
__device__ __forceinline__ void cpa_wait1() {
    asm volatile("cp.async.wait_group 1;\n");
}

// ldmatrix x4 (4 8x8 b16 tiles); p is this lane's row address
__device__ __forceinline__ void ldsm4(unsigned& r0, unsigned& r1,
                                      unsigned& r2, unsigned& r3,
                                      const __half* p) {
    unsigned a = (unsigned)__cvta_generic_to_shared(p);
    asm volatile("ldmatrix.sync.aligned.m8n8.x4.shared.b16 {%0,%1,%2,%3}, [%4];"
                 : "=r"(r0), "=r"(r1), "=r"(r2), "=r"(r3) : "r"(a));
}
__device__ __forceinline__ void ldsm4t(unsigned& r0, unsigned& r1,
                                       unsigned& r2, unsigned& r3,
                                       const __half* p) {
    unsigned a = (unsigned)__cvta_generic_to_shared(p);
    asm volatile("ldmatrix.sync.aligned.m8n8.x4.trans.shared.b16 {%0,%1,%2,%3}, [%4];"
                 : "=r"(r0), "=r"(r1), "=r"(r2), "=r"(r3) : "r"(a));
}
__device__ __forceinline__ unsigned ldu32(const __half* p) {
    return *(const unsigned*)p;
}

// mma.sync m16n8k16 fp16 -> fp32 accum, D += A*B
__device__ __forceinline__ void mma16(float* d, const unsigned* a, const unsigned* b) {
    asm volatile(
        "mma.sync.aligned.m16n8k16.row.col.f32.f16.f16.f32 "
        "{%0,%1,%2,%3}, {%4,%5,%6,%7}, {%8,%9}, {%0,%1,%2,%3};\n"
        : "+f"(d[0]), "+f"(d[1]), "+f"(d[2]), "+f"(d[3])
        : "r"(a[0]), "r"(a[1]), "r"(a[2]), "r"(a[3]), "r"(b[0]), "r"(b[1]));
}

// ----------------------------------------------------------------------------
// Input conversion: fp32 -> fp16, batched over q/k/v (grid.y)
// ----------------------------------------------------------------------------
struct CvtIn { const float* in[3]; __half* out[3]; };

__global__ __launch_bounds__(256) void cvt_in_kernel(CvtIn p, int n4)
{
    const float* in = p.in[blockIdx.y];
    __half* out     = p.out[blockIdx.y];
    int i = blockIdx.x * blockDim.x + threadIdx.x;
    if (i < n4) {
        float4 v = ((const float4*)in)[i];
        __half2 h2[2];
        h2[0] = __floats2half2_rn(v.x, v.y);
        h2[1] = __floats2half2_rn(v.z, v.w);
        ((uint2*)out)[i] = *(uint2*)h2;
    }
}

// ----------------------------------------------------------------------------
// Weight conversion: fp32 [k][n] -> fp16 TRANSPOSED [n][k], batched (grid.z)
// ----------------------------------------------------------------------------
struct CvtW { const float* in[4]; __half* out[4]; };

__global__ __launch_bounds__(256) void cvt_wt_kernel(CvtW p)
{
    const float* W = p.in[blockIdx.z];
    __half* Wt     = p.out[blockIdx.z];
    __shared__ float tile[32][33];
    const int n0 = blockIdx.x * 32, k0 = blockIdx.y * 32;
    const int tx = threadIdx.x & 31, ty4 = (threadIdx.x >> 5) * 4;
#pragma unroll
    for (int i = 0; i < 4; i++)
        tile[ty4 + i][tx] = W[(size_t)(k0 + ty4 + i) * DD + n0 + tx];
    __syncthreads();
#pragma unroll
    for (int i = 0; i < 4; i++)
        Wt[(size_t)(n0 + ty4 + i) * DD + k0 + tx] = __float2half_rn(tile[tx][ty4 + i]);
}

// ----------------------------------------------------------------------------
// fp16 tensor-core GEMM core: acc = A[128 rows][1024] @ Wt[128 cols][1024]^T
// 128x128x32 tile, 3-stage cp.async, 8 warps (4 m x 2 n), warp tile 32x64.
// All fragment loads via ldmatrix.x4.
// ----------------------------------------------------------------------------
#define GP 40                      // smem pitch in halves (32 + 8 pad)
#define GSTG (128 * GP)            // halves per tensor per stage
#define G_SMEM_BYTES (3 * 2 * GSTG * 2)

__device__ __forceinline__ void gemm16_core(
    const __half* __restrict__ A, const __half* __restrict__ Wt,
    float acc[2][8][4])
{
    extern __shared__ __half hsm[];
    __half* As = hsm;
    __half* Bs = hsm + 3 * GSTG;

    const int tid  = threadIdx.x;
    const int lane = tid & 31;
    const int wid  = tid >> 5;
    const int wm   = wid & 3;
    const int wn   = wid >> 2;
    const int row0 = blockIdx.y * 128;
    const int col0 = blockIdx.x * 128;

    // ldmatrix lane address patterns
    const int a_row = (lane & 7) + ((lane >> 3) & 1) * 8;  // A: tiles m0-7,m8-15 x k0,k8
    const int a_k   = (lane >> 4) * 8;
    const int b_row = (lane & 7) + (lane >> 4) * 8;        // B: tiles n0-7 x k0,k8; n8-15 x k0,k8
    const int b_k   = ((lane >> 3) & 1) * 8;

#pragma unroll
    for (int mt = 0; mt < 2; mt++)
#pragma unroll
        for (int nt = 0; nt < 8; nt++)
#pragma unroll
            for (int c = 0; c < 4; c++) acc[mt][nt][c] = 0.f;

    auto load_stage = [&](int s, int kt) {
        __half* Ap = As + s * GSTG;
        __half* Bp = Bs + s * GSTG;
#pragma unroll
        for (int j = 0; j < 2; j++) {
            int c = tid + 256 * j;        // 0..511
            int r = c >> 2, kc = c & 3;
            cpa16(Ap + r * GP + kc * 8, A  + (size_t)(row0 + r) * DD + kt * 32 + kc * 8);
            cpa16(Bp + r * GP + kc * 8, Wt + (size_t)(col0 + r) * DD + kt * 32 + kc * 8);
        }
    };

    const int NT = DD / 32;   // 32
    load_stage(0, 0); cpa_commit();
    load_stage(1, 1); cpa_commit();

    for (int it = 0; it < NT; it++) {
        cpa_wait1();
        __syncthreads();
        if (it + 2 < NT) load_stage((it + 2) % 3, it + 2);
        cpa_commit();

        const __half* Ac = As + (it % 3) * GSTG;
        const __half* Bc = Bs + (it % 3) * GSTG;
#pragma unroll
        for (int ks = 0; ks < 2; ks++) {
            const int k0 = ks * 16;
            unsigned a[2][4];
#pragma unroll
            for (int mt = 0; mt < 2; mt++)
                ldsm4(a[mt][0], a[mt][1], a[mt][2], a[mt][3],
                      Ac + (wm * 32 + mt * 16 + a_row) * GP + k0 + a_k);
            unsigned b[8][2];
#pragma unroll
            for (int np = 0; np < 4; np++)
                ldsm4(b[2 * np][0], b[2 * np][1], b[2 * np + 1][0], b[2 * np + 1][1],
                      Bc + (wn * 64 + np * 16 + b_row) * GP + k0 + b_k);
#pragma unroll
            for (int mt = 0; mt < 2; mt++)
#pragma unroll
                for (int nt = 0; nt < 8; nt++)
                    mma16(acc[mt][nt], a[mt], b[nt]);
        }
    }
}

// QKV batched projection: grid.z selects (A, Wt, bias, out16); z==0 also
// writes an fp32 residual copy and pre-scales the fp16 output by 1/8.
struct QkvArgs {
    const __half* A[3]; const __half* W[3]; const float* bias[3];
    __half* C16[3]; float* C32;
};

__global__ __launch_bounds__(256, 2) void qkv_gemm(QkvArgs ga)
{
    const int z = blockIdx.z;
    float acc[2][8][4];
    gemm16_core(ga.A[z], ga.W[z], acc);

    const int lane = threadIdx.x & 31;
    const int wid  = threadIdx.x >> 5;
    const int wm   = wid & 3, wn = wid >> 2;
    const int lq   = lane >> 2, lr = lane & 3;
    const int row0 = blockIdx.y * 128, col0 = blockIdx.x * 128;
    const float scale = (z == 0) ? 0.125f : 1.0f;
    const float* bias = ga.bias[z];
    __half* C16 = ga.C16[z];

#pragma unroll
    for (int mt = 0; mt < 2; mt++) {
#pragma unroll
        for (int nt = 0; nt < 8; nt++) {
            const int r  = row0 + wm * 32 + mt * 16 + lq;
            const int cb = col0 + wn * 64 + nt * 8 + 2 * lr;
            const float b0 = bias[cb], b1 = bias[cb + 1];
            float v00 = acc[mt][nt][0] + b0, v01 = acc[mt][nt][1] + b1;
            float v10 = acc[mt][nt][2] + b0, v11 = acc[mt][nt][3] + b1;
            *(__half2*)(C16 + (size_t)r * DD + cb) =
                __floats2half2_rn(v00 * scale, v01 * scale);
            *(__half2*)(C16 + (size_t)(r + 8) * DD + cb) =
                __floats2half2_rn(v10 * scale, v11 * scale);
            if (z == 0) {
                *(float2*)(ga.C32 + (size_t)r * DD + cb)       = make_float2(v00, v01);
                *(float2*)(ga.C32 + (size_t)(r + 8) * DD + cb) = make_float2(v10, v11);
            }
        }
    }
}

__global__ __launch_bounds__(256, 2) void fc_gemm(
    const __half* __restrict__ A, const __half* __restrict__ Wt,
    const float* __restrict__ bias, const float* __restrict__ res,
    float* __restrict__ C)
{
    float acc[2][8][4];
    gemm16_core(A, Wt, acc);

    const int lane = threadIdx.x & 31;
    const int wid  = threadIdx.x >> 5;
    const int wm   = wid & 3, wn = wid >> 2;
    const int lq   = lane >> 2, lr = lane & 3;
    const int row0 = blockIdx.y * 128, col0 = blockIdx.x * 128;

#pragma unroll
    for (int mt = 0; mt < 2; mt++) {
#pragma unroll
        for (int nt = 0; nt < 8; nt++) {
            const int r  = row0 + wm * 32 + mt * 16 + lq;
            const int cb = col0 + wn * 64 + nt * 8 + 2 * lr;
            const float b0 = bias[cb], b1 = bias[cb + 1];
            const float2 r0 = *(const float2*)(res + (size_t)r * DD + cb);
            const float2 r1 = *(const float2*)(res + (size_t)(r + 8) * DD + cb);
            *(float2*)(C + (size_t)r * DD + cb) =
                make_float2(acc[mt][nt][0] + b0 + r0.x, acc[mt][nt][1] + b1 + r0.y);
            *(float2*)(C + (size_t)(r + 8) * DD + cb) =
                make_float2(acc[mt][nt][2] + b0 + r1.x, acc[mt][nt][3] + b1 + r1.y);
        }
    }
}

// ----------------------------------------------------------------------------
// Flash attention, fp16 tensor cores, ldmatrix fragment loads.
// Block = (b*H+h, 128-row q tile), 256 threads (8 warps, 16 q-rows each).
// Q frags in registers (pre-scaled); K and V (natural [s][dv] layout)
// double-buffered cp.async; V B-frags via ldmatrix.trans; P via smem.
// ----------------------------------------------------------------------------
#define AP 72
#define A_KSTG (64 * AP)
#define A_SMEM_HALVES (4 * A_KSTG + 128 * AP)
#define A_SMEM_BYTES (A_SMEM_HALVES * 2)

__global__ __launch_bounds__(256, 2) void attn_tc(
    const __half* __restrict__ QP, const __half* __restrict__ KP,
    const __half* __restrict__ VP, __half* __restrict__ CTX)
{
    extern __shared__ __half asm16[];
    __half* KsBase = asm16;
    __half* VsBase = asm16 + 2 * A_KSTG;
    __half* Ps     = asm16 + 4 * A_KSTG;

    const int tid  = threadIdx.x;
    const int lane = tid & 31;
    const int wid  = tid >> 5;       // 0..7
    const int lq   = lane >> 2;      // 0..7
    const int lr   = lane & 3;       // 0..3
    const int bh   = blockIdx.y;
    const int b    = bh >> 4;
    const int h    = bh & 15;
    const int q0   = blockIdx.x * 128;

    // ldmatrix lane address patterns
    const int a_row = (lane & 7) + ((lane >> 3) & 1) * 8;
    const int a_k   = (lane >> 4) * 8;
    const int b_row = (lane & 7) + (lane >> 4) * 8;
    const int b_k   = ((lane >> 3) & 1) * 8;

    const __half* Kb = KP + (size_t)b * SS * DD + (size_t)h * 64;
    const __half* Vb = VP + (size_t)b * SS * DD + (size_t)h * 64;

    // Q fragments (already scaled by 1/8 in projection epilogue)
    unsigned qf[4][4];
    {
        const int r = q0 + wid * 16 + lq;
        const __half* qptr = QP + (size_t)(b * SS + r) * DD + h * 64;
#pragma unroll
        for (int kk = 0; kk < 4; kk++) {
            const __half* p = qptr + kk * 16 + 2 * lr;
            qf[kk][0] = ldu32(p);
            qf[kk][1] = ldu32(p + (size_t)8 * DD);
            qf[kk][2] = ldu32(p + 8);
            qf[kk][3] = ldu32(p + (size_t)8 * DD + 8);
        }
    }

    float o[8][4];
#pragma unroll
    for (int nt = 0; nt < 8; nt++)
#pragma unroll
        for (int c = 0; c < 4; c++) o[nt][c] = 0.f;
    float mrow[2] = {-INFINITY, -INFINITY};
    float lrow[2] = {0.f, 0.f};

    auto load_kv = [&](int s, int kt) {
        __half* Ks = KsBase + s * A_KSTG;
        __half* Vs = VsBase + s * A_KSTG;
#pragma unroll
        for (int j = 0; j < 2; j++) {
            int c = tid + 256 * j;        // 0..511
            int r = c >> 3, kc = c & 7;
            const size_t goff = (size_t)(kt * 64 + r) * DD + kc * 8;
            cpa16(Ks + r * AP + kc * 8, Kb + goff);
            cpa16(Vs + r * AP + kc * 8, Vb + goff);
        }
    };

    const int NT = SS / 64;   // 32
    load_kv(0, 0); cpa_commit();
    load_kv(1, 1); cpa_commit();

    for (int kt = 0; kt < NT; kt++) {
        cpa_wait1();
        __syncthreads();
        const __half* Kc = KsBase + (kt & 1) * A_KSTG;
        const __half* Vc = VsBase + (kt & 1) * A_KSTG;

        // S = (Q/8) K^T : 16x64 per warp
        float sacc[8][4];
#pragma unroll
        for (int nt = 0; nt < 8; nt++)
#pragma unroll
            for (int c = 0; c < 4; c++) sacc[nt][c] = 0.f;
#pragma unroll
        for (int kk = 0; kk < 4; kk++) {
            unsigned kb[8][2];
#pragma unroll
            for (int np = 0; np < 4; np++)
                ldsm4(kb[2 * np][0], kb[2 * np][1], kb[2 * np + 1][0], kb[2 * np + 1][1],
                      Kc + (np * 16 + b_row) * AP + kk * 16 + b_k);
#pragma unroll
            for (int nt = 0; nt < 8; nt++)
                mma16(sacc[nt], qf[kk], kb[nt]);
        }

        // online softmax (frag: c0,c1 -> row lq ; c2,c3 -> row lq+8)
#pragma unroll
        for (int r = 0; r < 2; r++) {
            float mx = -INFINITY;
#pragma unroll
            for (int nt = 0; nt < 8; nt++)
                mx = fmaxf(mx, fmaxf(sacc[nt][2 * r], sacc[nt][2 * r + 1]));
            mx = fmaxf(mx, __shfl_xor_sync(0xffffffffu, mx, 1));
            mx = fmaxf(mx, __shfl_xor_sync(0xffffffffu, mx, 2));
            float mnew  = fmaxf(mrow[r], mx);
            float alpha = __expf(mrow[r] - mnew);
            float ps = 0.f;
#pragma unroll
            for (int nt = 0; nt < 8; nt++) {
                float e0 = __expf(sacc[nt][2 * r] - mnew);
                float e1 = __expf(sacc[nt][2 * r + 1] - mnew);
                ps += e0 + e1;
                sacc[nt][2 * r] = e0; sacc[nt][2 * r + 1] = e1;
            }
            ps += __shfl_xor_sync(0xffffffffu, ps, 1);
            ps += __shfl_xor_sync(0xffffffffu, ps, 2);
            lrow[r] = lrow[r] * alpha + ps;
            mrow[r] = mnew;
#pragma unroll
            for (int nt = 0; nt < 8; nt++) {
                o[nt][2 * r]     *= alpha;
                o[nt][2 * r + 1] *= alpha;
            }
        }

        // store P as fp16 to smem (A-operand layout [m][kv])
        {
            const int pr0 = wid * 16 + lq;
#pragma unroll
            for (int nt = 0; nt < 8; nt++) {
                const int pc = nt * 8 + 2 * lr;
                *(__half2*)(Ps + pr0 * AP + pc) =
                    __floats2half2_rn(sacc[nt][0], sacc[nt][1]);
                *(__half2*)(Ps + (pr0 + 8) * AP + pc) =
                    __floats2half2_rn(sacc[nt][2], sacc[nt][3]);
            }
        }
        __syncthreads();

        // O += P V  (P a-frags via ldmatrix; V b-frags via ldmatrix.trans
        //  on the natural [s][dv] tile)
#pragma unroll
        for (int kk = 0; kk < 4; kk++) {
            unsigned pa[4];
            ldsm4(pa[0], pa[1], pa[2], pa[3],
                  Ps + (wid * 16 + a_row) * AP + kk * 16 + a_k);
            unsigned vb[8][2];
#pragma unroll
            for (int np = 0; np < 4; np++)
                ldsm4t(vb[2 * np][0], vb[2 * np][1], vb[2 * np + 1][0], vb[2 * np + 1][1],
                       Vc + (kk * 16 + a_row) * AP + np * 16 + a_k);
#pragma unroll
            for (int nt = 0; nt < 8; nt++)
                mma16(o[nt], pa, vb[nt]);
        }
        __syncthreads();   // all warps done with Ks/Vs/Ps before refill
        if (kt + 2 < NT) load_kv(kt & 1, kt + 2);
        cpa_commit();
    }

    // epilogue: normalize, store ctx fp16 in [B,S,H*DV]
    {
        const float inv0 = 1.f / lrow[0];
        const float inv1 = 1.f / lrow[1];
        const int r0 = q0 + wid * 16 + lq;
#pragma unroll
        for (int nt = 0; nt < 8; nt++) {
            const int col = h * 64 + nt * 8 + 2 * lr;
            *(__half2*)(CTX + (size_t)(b * SS + r0) * DD + col) =
                __floats2half2_rn(o[nt][0] * inv0, o[nt][1] * inv0);
            *(__half2*)(CTX + (size_t)(b * SS + r0 + 8) * DD + col) =
                __floats2half2_rn(o[nt][2] * inv1, o[nt][3] * inv1);
        }
    }
}

// ----------------------------------------------------------------------------
// LayerNorm: one block per row
// ----------------------------------------------------------------------------
__global__ __launch_bounds__(256) void ln_kernel(
    const float* __restrict__ X, const float* __restrict__ gamma,
    const float* __restrict__ beta, float* __restrict__ out)
{
    __shared__ float sh[18];
    const int row = blockIdx.x;
    const int tid = threadIdx.x;
    const float* xr = X + (size_t)row * DD;
    float4 v = *(const float4*)(xr + tid * 4);
    float s  = v.x + v.y + v.z + v.w;
    float sq = v.x * v.x + v.y * v.y + v.z * v.z + v.w * v.w;
#pragma unroll
    for (int off = 16; off; off >>= 1) {
        s  += __shfl_xor_sync(0xffffffffu, s, off);
        sq += __shfl_xor_sync(0xffffffffu, sq, off);
    }
    const int warp = tid >> 5;
    if ((tid & 31) == 0) { sh[warp] = s; sh[8 + warp] = sq; }
    __syncthreads();
    if (tid == 0) {
        float ts = 0.f, tq = 0.f;
#pragma unroll
        for (int w = 0; w < 8; w++) { ts += sh[w]; tq += sh[8 + w]; }
        float mu = ts * (1.f / DD);
        float var = tq * (1.f / DD) - mu * mu;
        sh[16] = mu;
        sh[17] = rsqrtf(var + 1e-5f);
    }
    __syncthreads();
    const float mu = sh[16], rstd = sh[17];
    float4 g = *(const float4*)(gamma + tid * 4);
    float4 bt = *(const float4*)(beta + tid * 4);
    float4 o;
    o.x = (v.x - mu) * rstd * g.x + bt.x;
    o.y = (v.y - mu) * rstd * g.y + bt.y;
    o.z = (v.z - mu) * rstd * g.z + bt.z;
    o.w = (v.w - mu) * rstd * g.w + bt.w;
    *(float4*)(out + (size_t)row * DD + tid * 4) = o;
}

// ----------------------------------------------------------------------------
// Launch
// ----------------------------------------------------------------------------
extern "C" void kernel_launch(void* const* d_in, const int* in_sizes, int n_in,
                              void* d_out, int out_size)
{
    const float* q     = (const float*)d_in[0];
    const float* k     = (const float*)d_in[1];
    const float* v     = (const float*)d_in[2];
    const float* Wq    = (const float*)d_in[3];
    const float* bq    = (const float*)d_in[4];
    const float* Wk    = (const float*)d_in[5];
    const float* bk    = (const float*)d_in[6];
    const float* Wv    = (const float*)d_in[7];
    const float* bv    = (const float*)d_in[8];
    const float* Wfc   = (const float*)d_in[9];
    const float* bfc   = (const float*)d_in[10];
    const float* gamma = (const float*)d_in[11];
    const float* beta  = (const float*)d_in[12];
    float* out = (float*)d_out;

    __half *q16, *k16, *v16, *qp16, *kp16, *vp16, *ctx16, *wq, *wk, *wv, *wfc;
    float *qp32, *xres;
    cudaGetSymbolAddress((void**)&q16,   g_q16);
    cudaGetSymbolAddress((void**)&k16,   g_k16);
    cudaGetSymbolAddress((void**)&v16,   g_v16);
    cudaGetSymbolAddress((void**)&qp16,  g_qp16);
    cudaGetSymbolAddress((void**)&kp16,  g_kp16);
    cudaGetSymbolAddress((void**)&vp16,  g_vp16);
    cudaGetSymbolAddress((void**)&ctx16, g_ctx16);
    cudaGetSymbolAddress((void**)&qp32,  g_qp32);
    cudaGetSymbolAddress((void**)&xres,  g_x);
    cudaGetSymbolAddress((void**)&wq,    g_wq);
    cudaGetSymbolAddress((void**)&wk,    g_wk);
    cudaGetSymbolAddress((void**)&wv,    g_wv);
    cudaGetSymbolAddress((void**)&wfc,   g_wfc);

    cudaFuncSetAttribute(qkv_gemm, cudaFuncAttributeMaxDynamicSharedMemorySize,
                         G_SMEM_BYTES);
    cudaFuncSetAttribute(fc_gemm, cudaFuncAttributeMaxDynamicSharedMemorySize,
                         G_SMEM_BYTES);
    cudaFuncSetAttribute(attn_tc, cudaFuncAttributeMaxDynamicSharedMemorySize,
                         A_SMEM_BYTES);

    // fp16 input conversion (batched q/k/v)
    CvtIn ci;
    ci.in[0] = q; ci.out[0] = q16;
    ci.in[1] = k; ci.out[1] = k16;
    ci.in[2] = v; ci.out[2] = v16;
    const int n4 = NELEM / 4;
    cvt_in_kernel<<<dim3(n4 / 256, 3), 256>>>(ci, n4);

    // fp16 transposed weight conversion (batched 4 weights)
    CvtW cw;
    cw.in[0] = Wq;  cw.out[0] = wq;
    cw.in[1] = Wk;  cw.out[1] = wk;
    cw.in[2] = Wv;  cw.out[2] = wv;
    cw.in[3] = Wfc; cw.out[3] = wfc;
    cvt_wt_kernel<<<dim3(DD / 32, DD / 32, 4), 256>>>(cw);

    // batched QKV projections
    QkvArgs ga;
    ga.A[0] = q16; ga.W[0] = wq; ga.bias[0] = bq; ga.C16[0] = qp16;
    ga.A[1] = k16; ga.W[1] = wk; ga.bias[1] = bk; ga.C16[1] = kp16;
    ga.A[2] = v16; ga.W[2] = wv; ga.bias[2] = bv; ga.C16[2] = vp16;
    ga.C32 = qp32;
    qkv_gemm<<<dim3(DD / 128, BS / 128, 3), 256, G_SMEM_BYTES>>>(ga);

    attn_tc<<<dim3(SS / 128, BB * HH), 256, A_SMEM_BYTES>>>(qp16, kp16, vp16, ctx16);

    fc_gemm<<<dim3(DD / 128, BS / 128), 256, G_SMEM_BYTES>>>(ctx16, wfc, bfc, qp32, xres);

    ln_kernel<<<BS, 256>>>(xres, gamma, beta, out);
}

// round 9
// speedup vs baseline: 8.6374x; 1.0359x over previous
#include <cuda_runtime.h>
#include <cuda_fp16.h>
#include <math.h>
#include <stdint.h>

// ----------------------------------------------------------------------------
// Problem constants
// ----------------------------------------------------------------------------
#define BB 4
#define SS 2048
#define DD 1024
#define HH 16
#define BS (BB * SS)            // 8192 rows
#define NELEM (BS * DD)         // 8388608

// ----------------------------------------------------------------------------
// Device scratch
// ----------------------------------------------------------------------------
__device__ __half g_q16[NELEM];     // fp16 inputs
__device__ __half g_k16[NELEM];
__device__ __half g_v16[NELEM];
__device__ __half g_qp16[NELEM];    // Q projection, pre-scaled by log2e/8
__device__ __half g_kp16[NELEM];
__device__ __half g_vp16[NELEM];
__device__ __half g_ctx16[NELEM];   // attention context
__device__ float  g_qp32[NELEM];    // fp32 residual copy of Q projection
__device__ float  g_x[NELEM];       // fc out + residual (pre-LN)
__device__ __half g_wq[DD * DD];    // fp16 TRANSPOSED weights [n][k]
__device__ __half g_wk[DD * DD];
__device__ __half g_wv[DD * DD];
__device__ __half g_wfc[DD * DD];

// ----------------------------------------------------------------------------
// Helpers
// ----------------------------------------------------------------------------
__device__ __forceinline__ void cpa16(void* dst, const void* src) {
    unsigned d = (unsigned)__cvta_generic_to_shared(dst);
    asm volatile("cp.async.cg.shared.global [%0], [%1], 16;\n" :: "r"(d), "l"(src));
}
__device__ __forceinline__ void cpa_commit() {
    asm volatile("cp.async.commit_group;\n");
}
__device__ __forceinline__ void cpa_wait1() {
    asm volatile("cp.async.wait_group 1;\n");
}

// ldmatrix x4 (4 8x8 b16 tiles); p is this lane's row address
__device__ __forceinline__ void ldsm4(unsigned& r0, unsigned& r1,
                                      unsigned& r2, unsigned& r3,
                                      const __half* p) {
    unsigned a = (unsigned)__cvta_generic_to_shared(p);
    asm volatile("ldmatrix.sync.aligned.m8n8.x4.shared.b16 {%0,%1,%2,%3}, [%4];"
                 : "=r"(r0), "=r"(r1), "=r"(r2), "=r"(r3) : "r"(a));
}
__device__ __forceinline__ void ldsm4t(unsigned& r0, unsigned& r1,
                                       unsigned& r2, unsigned& r3,
                                       const __half* p) {
    unsigned a = (unsigned)__cvta_generic_to_shared(p);
    asm volatile("ldmatrix.sync.aligned.m8n8.x4.trans.shared.b16 {%0,%1,%2,%3}, [%4];"
                 : "=r"(r0), "=r"(r1), "=r"(r2), "=r"(r3) : "r"(a));
}
__device__ __forceinline__ unsigned ldu32(const __half* p) {
    return *(const unsigned*)p;
}

// packed fp16 2^x
__device__ __forceinline__ unsigned h2exp2u(unsigned x) {
    unsigned r;
    asm("ex2.approx.f16x2 %0, %1;" : "=r"(r) : "r"(x));
    return r;
}

// mma.sync m16n8k16 fp16 -> fp32 accum, D += A*B
__device__ __forceinline__ void mma16(float* d, const unsigned* a, const unsigned* b) {
    asm volatile(
        "mma.sync.aligned.m16n8k16.row.col.f32.f16.f16.f32 "
        "{%0,%1,%2,%3}, {%4,%5,%6,%7}, {%8,%9}, {%0,%1,%2,%3};\n"
        : "+f"(d[0]), "+f"(d[1]), "+f"(d[2]), "+f"(d[3])
        : "r"(a[0]), "r"(a[1]), "r"(a[2]), "r"(a[3]), "r"(b[0]), "r"(b[1]));
}

// ----------------------------------------------------------------------------
// Input conversion: fp32 -> fp16, batched over q/k/v (grid.y)
// ----------------------------------------------------------------------------
struct CvtIn { const float* in[3]; __half* out[3]; };

__global__ __launch_bounds__(256) void cvt_in_kernel(CvtIn p, int n4)
{
    const float* in = p.in[blockIdx.y];
    __half* out     = p.out[blockIdx.y];
    int i = blockIdx.x * blockDim.x + threadIdx.x;
    if (i < n4) {
        float4 v = ((const float4*)in)[i];
        __half2 h2[2];
        h2[0] = __floats2half2_rn(v.x, v.y);
        h2[1] = __floats2half2_rn(v.z, v.w);
        ((uint2*)out)[i] = *(uint2*)h2;
    }
}

// ----------------------------------------------------------------------------
// Weight conversion: fp32 [k][n] -> fp16 TRANSPOSED [n][k], batched (grid.z)
// ----------------------------------------------------------------------------
struct CvtW { const float* in[4]; __half* out[4]; };

__global__ __launch_bounds__(256) void cvt_wt_kernel(CvtW p)
{
    const float* W = p.in[blockIdx.z];
    __half* Wt     = p.out[blockIdx.z];
    __shared__ float tile[32][33];
    const int n0 = blockIdx.x * 32, k0 = blockIdx.y * 32;
    const int tx = threadIdx.x & 31, ty4 = (threadIdx.x >> 5) * 4;
#pragma unroll
    for (int i = 0; i < 4; i++)
        tile[ty4 + i][tx] = W[(size_t)(k0 + ty4 + i) * DD + n0 + tx];
    __syncthreads();
#pragma unroll
    for (int i = 0; i < 4; i++)
        Wt[(size_t)(n0 + ty4 + i) * DD + k0 + tx] = __float2half_rn(tile[tx][ty4 + i]);
}

// ----------------------------------------------------------------------------
// fp16 tensor-core GEMM core: acc = A[128 rows][1024] @ Wt[128 cols][1024]^T
// 128x128x32 tile, 3-stage cp.async, 8 warps (4 m x 2 n), warp tile 32x64.
// ----------------------------------------------------------------------------
#define GP 40                      // smem pitch in halves (32 + 8 pad)
#define GSTG (128 * GP)            // halves per tensor per stage
#define G_SMEM_BYTES (3 * 2 * GSTG * 2)

__device__ __forceinline__ void gemm16_core(
    const __half* __restrict__ A, const __half* __restrict__ Wt,
    float acc[2][8][4])
{
    extern __shared__ __half hsm[];
    __half* As = hsm;
    __half* Bs = hsm + 3 * GSTG;

    const int tid  = threadIdx.x;
    const int lane = tid & 31;
    const int wid  = tid >> 5;
    const int wm   = wid & 3;
    const int wn   = wid >> 2;
    const int row0 = blockIdx.y * 128;
    const int col0 = blockIdx.x * 128;

    const int a_row = (lane & 7) + ((lane >> 3) & 1) * 8;
    const int a_k   = (lane >> 4) * 8;
    const int b_row = (lane & 7) + (lane >> 4) * 8;
    const int b_k   = ((lane >> 3) & 1) * 8;

#pragma unroll
    for (int mt = 0; mt < 2; mt++)
#pragma unroll
        for (int nt = 0; nt < 8; nt++)
#pragma unroll
            for (int c = 0; c < 4; c++) acc[mt][nt][c] = 0.f;

    auto load_stage = [&](int s, int kt) {
        __half* Ap = As + s * GSTG;
        __half* Bp = Bs + s * GSTG;
#pragma unroll
        for (int j = 0; j < 2; j++) {
            int c = tid + 256 * j;
            int r = c >> 2, kc = c & 3;
            cpa16(Ap + r * GP + kc * 8, A  + (size_t)(row0 + r) * DD + kt * 32 + kc * 8);
            cpa16(Bp + r * GP + kc * 8, Wt + (size_t)(col0 + r) * DD + kt * 32 + kc * 8);
        }
    };

    const int NT = DD / 32;   // 32
    load_stage(0, 0); cpa_commit();
    load_stage(1, 1); cpa_commit();

    for (int it = 0; it < NT; it++) {
        cpa_wait1();
        __syncthreads();
        if (it + 2 < NT) load_stage((it + 2) % 3, it + 2);
        cpa_commit();

        const __half* Ac = As + (it % 3) * GSTG;
        const __half* Bc = Bs + (it % 3) * GSTG;
#pragma unroll
        for (int ks = 0; ks < 2; ks++) {
            const int k0 = ks * 16;
            unsigned a[2][4];
#pragma unroll
            for (int mt = 0; mt < 2; mt++)
                ldsm4(a[mt][0], a[mt][1], a[mt][2], a[mt][3],
                      Ac + (wm * 32 + mt * 16 + a_row) * GP + k0 + a_k);
            unsigned b[8][2];
#pragma unroll
            for (int np = 0; np < 4; np++)
                ldsm4(b[2 * np][0], b[2 * np][1], b[2 * np + 1][0], b[2 * np + 1][1],
                      Bc + (wn * 64 + np * 16 + b_row) * GP + k0 + b_k);
#pragma unroll
            for (int mt = 0; mt < 2; mt++)
#pragma unroll
                for (int nt = 0; nt < 8; nt++)
                    mma16(acc[mt][nt], a[mt], b[nt]);
        }
    }
}

// QKV batched projection: grid.z selects (A, Wt, bias, out16); z==0 also
// writes an fp32 residual copy and pre-scales fp16 out by log2e/8.
struct QkvArgs {
    const __half* A[3]; const __half* W[3]; const float* bias[3];
    __half* C16[3]; float* C32;
};

__global__ __launch_bounds__(256, 2) void qkv_gemm(QkvArgs ga)
{
    const int z = blockIdx.z;
    float acc[2][8][4];
    gemm16_core(ga.A[z], ga.W[z], acc);

    const int lane = threadIdx.x & 31;
    const int wid  = threadIdx.x >> 5;
    const int wm   = wid & 3, wn = wid >> 2;
    const int lq   = lane >> 2, lr = lane & 3;
    const int row0 = blockIdx.y * 128, col0 = blockIdx.x * 128;
    const float scale = (z == 0) ? 0.125f * 1.44269504f : 1.0f;
    const float* bias = ga.bias[z];
    __half* C16 = ga.C16[z];

#pragma unroll
    for (int mt = 0; mt < 2; mt++) {
#pragma unroll
        for (int nt = 0; nt < 8; nt++) {
            const int r  = row0 + wm * 32 + mt * 16 + lq;
            const int cb = col0 + wn * 64 + nt * 8 + 2 * lr;
            const float b0 = bias[cb], b1 = bias[cb + 1];
            float v00 = acc[mt][nt][0] + b0, v01 = acc[mt][nt][1] + b1;
            float v10 = acc[mt][nt][2] + b0, v11 = acc[mt][nt][3] + b1;
            *(__half2*)(C16 + (size_t)r * DD + cb) =
                __floats2half2_rn(v00 * scale, v01 * scale);
            *(__half2*)(C16 + (size_t)(r + 8) * DD + cb) =
                __floats2half2_rn(v10 * scale, v11 * scale);
            if (z == 0) {
                *(float2*)(ga.C32 + (size_t)r * DD + cb)       = make_float2(v00, v01);
                *(float2*)(ga.C32 + (size_t)(r + 8) * DD + cb) = make_float2(v10, v11);
            }
        }
    }
}

__global__ __launch_bounds__(256, 2) void fc_gemm(
    const __half* __restrict__ A, const __half* __restrict__ Wt,
    const float* __restrict__ bias, const float* __restrict__ res,
    float* __restrict__ C)
{
    float acc[2][8][4];
    gemm16_core(A, Wt, acc);

    const int lane = threadIdx.x & 31;
    const int wid  = threadIdx.x >> 5;
    const int wm   = wid & 3, wn = wid >> 2;
    const int lq   = lane >> 2, lr = lane & 3;
    const int row0 = blockIdx.y * 128, col0 = blockIdx.x * 128;

#pragma unroll
    for (int mt = 0; mt < 2; mt++) {
#pragma unroll
        for (int nt = 0; nt < 8; nt++) {
            const int r  = row0 + wm * 32 + mt * 16 + lq;
            const int cb = col0 + wn * 64 + nt * 8 + 2 * lr;
            const float b0 = bias[cb], b1 = bias[cb + 1];
            const float2 r0 = *(const float2*)(res + (size_t)r * DD + cb);
            const float2 r1 = *(const float2*)(res + (size_t)(r + 8) * DD + cb);
            *(float2*)(C + (size_t)r * DD + cb) =
                make_float2(acc[mt][nt][0] + b0 + r0.x, acc[mt][nt][1] + b1 + r0.y);
            *(float2*)(C + (size_t)(r + 8) * DD + cb) =
                make_float2(acc[mt][nt][2] + b0 + r1.x, acc[mt][nt][3] + b1 + r1.y);
        }
    }
}

// ----------------------------------------------------------------------------
// Flash attention, fp16 tensor cores, base-2 packed-fp16 softmax.
// Block = (b*H+h, 128-row q tile), 256 threads (8 warps, 16 q-rows each).
// 3-stage K/V ring (2 syncs/iter); next tile's cp.async issued after S-mma.
// ----------------------------------------------------------------------------
#define AP 72
#define A_KSTG (64 * AP)
#define A_SMEM_HALVES (6 * A_KSTG + 128 * AP)
#define A_SMEM_BYTES (A_SMEM_HALVES * 2)

__global__ __launch_bounds__(256, 2) void attn_tc(
    const __half* __restrict__ QP, const __half* __restrict__ KP,
    const __half* __restrict__ VP, __half* __restrict__ CTX)
{
    extern __shared__ __half asm16[];
    __half* KsBase = asm16;                    // 3 stages
    __half* VsBase = asm16 + 3 * A_KSTG;       // 3 stages
    __half* Ps     = asm16 + 6 * A_KSTG;

    const int tid  = threadIdx.x;
    const int lane = tid & 31;
    const int wid  = tid >> 5;       // 0..7
    const int lq   = lane >> 2;      // 0..7
    const int lr   = lane & 3;       // 0..3
    const int bh   = blockIdx.y;
    const int b    = bh >> 4;
    const int h    = bh & 15;
    const int q0   = blockIdx.x * 128;

    const int a_row = (lane & 7) + ((lane >> 3) & 1) * 8;
    const int a_k   = (lane >> 4) * 8;
    const int b_row = (lane & 7) + (lane >> 4) * 8;
    const int b_k   = ((lane >> 3) & 1) * 8;

    const __half* Kb = KP + (size_t)b * SS * DD + (size_t)h * 64;
    const __half* Vb = VP + (size_t)b * SS * DD + (size_t)h * 64;

    // Q fragments (pre-scaled by log2e/8 in projection epilogue)
    unsigned qf[4][4];
    {
        const int r = q0 + wid * 16 + lq;
        const __half* qptr = QP + (size_t)(b * SS + r) * DD + h * 64;
#pragma unroll
        for (int kk = 0; kk < 4; kk++) {
            const __half* p = qptr + kk * 16 + 2 * lr;
            qf[kk][0] = ldu32(p);
            qf[kk][1] = ldu32(p + (size_t)8 * DD);
            qf[kk][2] = ldu32(p + 8);
            qf[kk][3] = ldu32(p + (size_t)8 * DD + 8);
        }
    }

    float o[8][4];
#pragma unroll
    for (int nt = 0; nt < 8; nt++)
#pragma unroll
        for (int c = 0; c < 4; c++) o[nt][c] = 0.f;
    float mrow[2] = {-INFINITY, -INFINITY};
    float lrow[2] = {0.f, 0.f};

    auto load_kv = [&](int s, int kt) {
        __half* Ks = KsBase + s * A_KSTG;
        __half* Vs = VsBase + s * A_KSTG;
#pragma unroll
        for (int j = 0; j < 2; j++) {
            int c = tid + 256 * j;        // 0..511
            int r = c >> 3, kc = c & 7;
            const size_t goff = (size_t)(kt * 64 + r) * DD + kc * 8;
            cpa16(Ks + r * AP + kc * 8, Kb + goff);
            cpa16(Vs + r * AP + kc * 8, Vb + goff);
        }
    };

    const int NT = SS / 64;   // 32
    load_kv(0, 0); cpa_commit();
    load_kv(1, 1); cpa_commit();

    for (int kt = 0; kt < NT; kt++) {
        cpa_wait1();
        __syncthreads();   // stage kt ready; all warps done with prev PV/Ps
        const int st = kt % 3;
        const __half* Kc = KsBase + st * A_KSTG;
        const __half* Vc = VsBase + st * A_KSTG;

        // S = (log2e/8 * Q) K^T : 16x64 per warp (base-2 logits)
        float sacc[8][4];
#pragma unroll
        for (int nt = 0; nt < 8; nt++)
#pragma unroll
            for (int c = 0; c < 4; c++) sacc[nt][c] = 0.f;
#pragma unroll
        for (int kk = 0; kk < 4; kk++) {
            unsigned kb[8][2];
#pragma unroll
            for (int np = 0; np < 4; np++)
                ldsm4(kb[2 * np][0], kb[2 * np][1], kb[2 * np + 1][0], kb[2 * np + 1][1],
                      Kc + (np * 16 + b_row) * AP + kk * 16 + b_k);
#pragma unroll
            for (int nt = 0; nt < 8; nt++)
                mma16(sacc[nt], qf[kk], kb[nt]);
        }

        // prefetch next tile under softmax+PV (stage (kt+2)%3 is idle)
        if (kt + 2 < NT) { load_kv((kt + 2) % 3, kt + 2); }
        cpa_commit();

        // base-2 online softmax; P computed packed fp16 via ex2.approx.f16x2
#pragma unroll
        for (int r = 0; r < 2; r++) {
            float mx = -INFINITY;
#pragma unroll
            for (int nt = 0; nt < 8; nt++)
                mx = fmaxf(mx, fmaxf(sacc[nt][2 * r], sacc[nt][2 * r + 1]));
            mx = fmaxf(mx, __shfl_xor_sync(0xffffffffu, mx, 1));
            mx = fmaxf(mx, __shfl_xor_sync(0xffffffffu, mx, 2));
            const bool ch = mx > mrow[r];
            const float mnew = ch ? mx : mrow[r];
            if (__any_sync(0xffffffffu, ch)) {
                const float alpha = exp2f(mrow[r] - mnew);
                lrow[r] *= alpha;
#pragma unroll
                for (int nt = 0; nt < 8; nt++) {
                    o[nt][2 * r]     *= alpha;
                    o[nt][2 * r + 1] *= alpha;
                }
                mrow[r] = mnew;
            }
            float ps = 0.f;
            const int prr = wid * 16 + lq + r * 8;
#pragma unroll
            for (int nt = 0; nt < 8; nt++) {
                __half2 d = __floats2half2_rn(sacc[nt][2 * r] - mnew,
                                              sacc[nt][2 * r + 1] - mnew);
                unsigned e = h2exp2u(*(unsigned*)&d);
                *(unsigned*)(Ps + prr * AP + nt * 8 + 2 * lr) = e;
                float2 f = __half22float2(*(__half2*)&e);
                ps += f.x + f.y;
            }
            ps += __shfl_xor_sync(0xffffffffu, ps, 1);
            ps += __shfl_xor_sync(0xffffffffu, ps, 2);
            lrow[r] += ps;
        }
        __syncthreads();   // Ps visible to all warps

        // O += P V  (P a-frags via ldmatrix; V b-frags via ldmatrix.trans)
#pragma unroll
        for (int kk = 0; kk < 4; kk++) {
            unsigned pa[4];
            ldsm4(pa[0], pa[1], pa[2], pa[3],
                  Ps + (wid * 16 + a_row) * AP + kk * 16 + a_k);
            unsigned vb[8][2];
#pragma unroll
            for (int np = 0; np < 4; np++)
                ldsm4t(vb[2 * np][0], vb[2 * np][1], vb[2 * np + 1][0], vb[2 * np + 1][1],
                       Vc + (kk * 16 + a_row) * AP + np * 16 + a_k);
#pragma unroll
            for (int nt = 0; nt < 8; nt++)
                mma16(o[nt], pa, vb[nt]);
        }
    }

    // epilogue: normalize, store ctx fp16 in [B,S,H*DV]
    {
        const float inv0 = 1.f / lrow[0];
        const float inv1 = 1.f / lrow[1];
        const int r0 = q0 + wid * 16 + lq;
#pragma unroll
        for (int nt = 0; nt < 8; nt++) {
            const int col = h * 64 + nt * 8 + 2 * lr;
            *(__half2*)(CTX + (size_t)(b * SS + r0) * DD + col) =
                __floats2half2_rn(o[nt][0] * inv0, o[nt][1] * inv0);
            *(__half2*)(CTX + (size_t)(b * SS + r0 + 8) * DD + col) =
                __floats2half2_rn(o[nt][2] * inv1, o[nt][3] * inv1);
        }
    }
}

// ----------------------------------------------------------------------------
// LayerNorm: one block per row
// ----------------------------------------------------------------------------
__global__ __launch_bounds__(256) void ln_kernel(
    const float* __restrict__ X, const float* __restrict__ gamma,
    const float* __restrict__ beta, float* __restrict__ out)
{
    __shared__ float sh[18];
    const int row = blockIdx.x;
    const int tid = threadIdx.x;
    const float* xr = X + (size_t)row * DD;
    float4 v = *(const float4*)(xr + tid * 4);
    float s  = v.x + v.y + v.z + v.w;
    float sq = v.x * v.x + v.y * v.y + v.z * v.z + v.w * v.w;
#pragma unroll
    for (int off = 16; off; off >>= 1) {
        s  += __shfl_xor_sync(0xffffffffu, s, off);
        sq += __shfl_xor_sync(0xffffffffu, sq, off);
    }
    const int warp = tid >> 5;
    if ((tid & 31) == 0) { sh[warp] = s; sh[8 + warp] = sq; }
    __syncthreads();
    if (tid == 0) {
        float ts = 0.f, tq = 0.f;
#pragma unroll
        for (int w = 0; w < 8; w++) { ts += sh[w]; tq += sh[8 + w]; }
        float mu = ts * (1.f / DD);
        float var = tq * (1.f / DD) - mu * mu;
        sh[16] = mu;
        sh[17] = rsqrtf(var + 1e-5f);
    }
    __syncthreads();
    const float mu = sh[16], rstd = sh[17];
    float4 g = *(const float4*)(gamma + tid * 4);
    float4 bt = *(const float4*)(beta + tid * 4);
    float4 o;
    o.x = (v.x - mu) * rstd * g.x + bt.x;
    o.y = (v.y - mu) * rstd * g.y + bt.y;
    o.z = (v.z - mu) * rstd * g.z + bt.z;
    o.w = (v.w - mu) * rstd * g.w + bt.w;
    *(float4*)(out + (size_t)row * DD + tid * 4) = o;
}

// ----------------------------------------------------------------------------
// Launch
// ----------------------------------------------------------------------------
extern "C" void kernel_launch(void* const* d_in, const int* in_sizes, int n_in,
                              void* d_out, int out_size)
{
    const float* q     = (const float*)d_in[0];
    const float* k     = (const float*)d_in[1];
    const float* v     = (const float*)d_in[2];
    const float* Wq    = (const float*)d_in[3];
    const float* bq    = (const float*)d_in[4];
    const float* Wk    = (const float*)d_in[5];
    const float* bk    = (const float*)d_in[6];
    const float* Wv    = (const float*)d_in[7];
    const float* bv    = (const float*)d_in[8];
    const float* Wfc   = (const float*)d_in[9];
    const float* bfc   = (const float*)d_in[10];
    const float* gamma = (const float*)d_in[11];
    const float* beta  = (const float*)d_in[12];
    float* out = (float*)d_out;

    __half *q16, *k16, *v16, *qp16, *kp16, *vp16, *ctx16, *wq, *wk, *wv, *wfc;
    float *qp32, *xres;
    cudaGetSymbolAddress((void**)&q16,   g_q16);
    cudaGetSymbolAddress((void**)&k16,   g_k16);
    cudaGetSymbolAddress((void**)&v16,   g_v16);
    cudaGetSymbolAddress((void**)&qp16,  g_qp16);
    cudaGetSymbolAddress((void**)&kp16,  g_kp16);
    cudaGetSymbolAddress((void**)&vp16,  g_vp16);
    cudaGetSymbolAddress((void**)&ctx16, g_ctx16);
    cudaGetSymbolAddress((void**)&qp32,  g_qp32);
    cudaGetSymbolAddress((void**)&xres,  g_x);
    cudaGetSymbolAddress((void**)&wq,    g_wq);
    cudaGetSymbolAddress((void**)&wk,    g_wk);
    cudaGetSymbolAddress((void**)&wv,    g_wv);
    cudaGetSymbolAddress((void**)&wfc,   g_wfc);

    cudaFuncSetAttribute(qkv_gemm, cudaFuncAttributeMaxDynamicSharedMemorySize,
                         G_SMEM_BYTES);
    cudaFuncSetAttribute(fc_gemm, cudaFuncAttributeMaxDynamicSharedMemorySize,
                         G_SMEM_BYTES);
    cudaFuncSetAttribute(attn_tc, cudaFuncAttributeMaxDynamicSharedMemorySize,
                         A_SMEM_BYTES);

    // fp16 input conversion (batched q/k/v)
    CvtIn ci;
    ci.in[0] = q; ci.out[0] = q16;
    ci.in[1] = k; ci.out[1] = k16;
    ci.in[2] = v; ci.out[2] = v16;
    const int n4 = NELEM / 4;
    cvt_in_kernel<<<dim3(n4 / 256, 3), 256>>>(ci, n4);

    // fp16 transposed weight conversion (batched 4 weights)
    CvtW cw;
    cw.in[0] = Wq;  cw.out[0] = wq;
    cw.in[1] = Wk;  cw.out[1] = wk;
    cw.in[2] = Wv;  cw.out[2] = wv;
    cw.in[3] = Wfc; cw.out[3] = wfc;
    cvt_wt_kernel<<<dim3(DD / 32, DD / 32, 4), 256>>>(cw);

    // batched QKV projections
    QkvArgs ga;
    ga.A[0] = q16; ga.W[0] = wq; ga.bias[0] = bq; ga.C16[0] = qp16;
    ga.A[1] = k16; ga.W[1] = wk; ga.bias[1] = bk; ga.C16[1] = kp16;
    ga.A[2] = v16; ga.W[2] = wv; ga.bias[2] = bv; ga.C16[2] = vp16;
    ga.C32 = qp32;
    qkv_gemm<<<dim3(DD / 128, BS / 128, 3), 256, G_SMEM_BYTES>>>(ga);

    attn_tc<<<dim3(SS / 128, BB * HH), 256, A_SMEM_BYTES>>>(qp16, kp16, vp16, ctx16);

    fc_gemm<<<dim3(DD / 128, BS / 128), 256, G_SMEM_BYTES>>>(ctx16, wfc, bfc, qp32, xres);

    ln_kernel<<<BS, 256>>>(xres, gamma, beta, out);
}

// round 10
// speedup vs baseline: 9.1338x; 1.0575x over previous
#include <cuda_runtime.h>
#include <cuda_fp16.h>
#include <math.h>
#include <stdint.h>

// ----------------------------------------------------------------------------
// Problem constants
// ----------------------------------------------------------------------------
#define BB 4
#define SS 2048
#define DD 1024
#define HH 16
#define BS (BB * SS)            // 8192 rows
#define NELEM (BS * DD)         // 8388608

// ----------------------------------------------------------------------------
// Device scratch
// ----------------------------------------------------------------------------
__device__ __half g_q16[NELEM];     // fp16 inputs
__device__ __half g_k16[NELEM];
__device__ __half g_v16[NELEM];
__device__ __half g_qp16[NELEM];    // Q projection, pre-scaled by log2e/8
__device__ __half g_kp16[NELEM];
__device__ __half g_vp16[NELEM];
__device__ __half g_ctx16[NELEM];   // attention context
__device__ float  g_qp32[NELEM];    // fp32 residual copy of Q projection
__device__ float  g_x[NELEM];       // fc out + residual (pre-LN)
__device__ __half g_wq[DD * DD];    // fp16 TRANSPOSED weights [n][k]
__device__ __half g_wk[DD * DD];
__device__ __half g_wv[DD * DD];
__device__ __half g_wfc[DD * DD];

// ----------------------------------------------------------------------------
// Helpers
// ----------------------------------------------------------------------------
__device__ __forceinline__ void cpa16(void* dst, const void* src) {
    unsigned d = (unsigned)__cvta_generic_to_shared(dst);
    asm volatile("cp.async.cg.shared.global [%0], [%1], 16;\n" :: "r"(d), "l"(src));
}
__device__ __forceinline__ void cpa_commit() {
    asm volatile("cp.async.commit_group;\n");
}
__device__ __forceinline__ void cpa_wait1() {
    asm volatile("cp.async.wait_group 1;\n");
}

// ldmatrix x4 (4 8x8 b16 tiles); p is this lane's row address
__device__ __forceinline__ void ldsm4(unsigned& r0, unsigned& r1,
                                      unsigned& r2, unsigned& r3,
                                      const __half* p) {
    unsigned a = (unsigned)__cvta_generic_to_shared(p);
    asm volatile("ldmatrix.sync.aligned.m8n8.x4.shared.b16 {%0,%1,%2,%3}, [%4];"
                 : "=r"(r0), "=r"(r1), "=r"(r2), "=r"(r3) : "r"(a));
}
__device__ __forceinline__ void ldsm4t(unsigned& r0, unsigned& r1,
                                       unsigned& r2, unsigned& r3,
                                       const __half* p) {
    unsigned a = (unsigned)__cvta_generic_to_shared(p);
    asm volatile("ldmatrix.sync.aligned.m8n8.x4.trans.shared.b16 {%0,%1,%2,%3}, [%4];"
                 : "=r"(r0), "=r"(r1), "=r"(r2), "=r"(r3) : "r"(a));
}
__device__ __forceinline__ unsigned ldu32(const __half* p) {
    return *(const unsigned*)p;
}

// packed fp16 2^x
__device__ __forceinline__ unsigned h2exp2u(unsigned x) {
    unsigned r;
    asm("ex2.approx.f16x2 %0, %1;" : "=r"(r) : "r"(x));
    return r;
}

// mma.sync m16n8k16 fp16 -> fp32 accum, D += A*B
__device__ __forceinline__ void mma16(float* d, const unsigned* a, const unsigned* b) {
    asm volatile(
        "mma.sync.aligned.m16n8k16.row.col.f32.f16.f16.f32 "
        "{%0,%1,%2,%3}, {%4,%5,%6,%7}, {%8,%9}, {%0,%1,%2,%3};\n"
        : "+f"(d[0]), "+f"(d[1]), "+f"(d[2]), "+f"(d[3])
        : "r"(a[0]), "r"(a[1]), "r"(a[2]), "r"(a[3]), "r"(b[0]), "r"(b[1]));
}

// ----------------------------------------------------------------------------
// Input conversion: fp32 -> fp16, batched over q/k/v (grid.y)
// ----------------------------------------------------------------------------
struct CvtIn { const float* in[3]; __half* out[3]; };

__global__ __launch_bounds__(256) void cvt_in_kernel(CvtIn p, int n4)
{
    const float* in = p.in[blockIdx.y];
    __half* out     = p.out[blockIdx.y];
    int i = blockIdx.x * blockDim.x + threadIdx.x;
    if (i < n4) {
        float4 v = ((const float4*)in)[i];
        __half2 h2[2];
        h2[0] = __floats2half2_rn(v.x, v.y);
        h2[1] = __floats2half2_rn(v.z, v.w);
        ((uint2*)out)[i] = *(uint2*)h2;
    }
}

// ----------------------------------------------------------------------------
// Weight conversion: fp32 [k][n] -> fp16 TRANSPOSED [n][k], batched (grid.z)
// ----------------------------------------------------------------------------
struct CvtW { const float* in[4]; __half* out[4]; };

__global__ __launch_bounds__(256) void cvt_wt_kernel(CvtW p)
{
    const float* W = p.in[blockIdx.z];
    __half* Wt     = p.out[blockIdx.z];
    __shared__ float tile[32][33];
    const int n0 = blockIdx.x * 32, k0 = blockIdx.y * 32;
    const int tx = threadIdx.x & 31, ty4 = (threadIdx.x >> 5) * 4;
#pragma unroll
    for (int i = 0; i < 4; i++)
        tile[ty4 + i][tx] = W[(size_t)(k0 + ty4 + i) * DD + n0 + tx];
    __syncthreads();
#pragma unroll
    for (int i = 0; i < 4; i++)
        Wt[(size_t)(n0 + ty4 + i) * DD + k0 + tx] = __float2half_rn(tile[tx][ty4 + i]);
}

// ----------------------------------------------------------------------------
// fp16 tensor-core GEMM core: acc = A[128 rows][1024] @ Wt[128 cols][1024]^T
// 128x128x32 tile, 3-stage cp.async, 8 warps (4 m x 2 n), warp tile 32x64.
// ----------------------------------------------------------------------------
#define GP 40                      // smem pitch in halves (32 + 8 pad)
#define GSTG (128 * GP)            // halves per tensor per stage
#define G_SMEM_BYTES (3 * 2 * GSTG * 2)

__device__ __forceinline__ void gemm16_core(
    const __half* __restrict__ A, const __half* __restrict__ Wt,
    float acc[2][8][4])
{
    extern __shared__ __half hsm[];
    __half* As = hsm;
    __half* Bs = hsm + 3 * GSTG;

    const int tid  = threadIdx.x;
    const int lane = tid & 31;
    const int wid  = tid >> 5;
    const int wm   = wid & 3;
    const int wn   = wid >> 2;
    const int row0 = blockIdx.y * 128;
    const int col0 = blockIdx.x * 128;

    const int a_row = (lane & 7) + ((lane >> 3) & 1) * 8;
    const int a_k   = (lane >> 4) * 8;
    const int b_row = (lane & 7) + (lane >> 4) * 8;
    const int b_k   = ((lane >> 3) & 1) * 8;

#pragma unroll
    for (int mt = 0; mt < 2; mt++)
#pragma unroll
        for (int nt = 0; nt < 8; nt++)
#pragma unroll
            for (int c = 0; c < 4; c++) acc[mt][nt][c] = 0.f;

    auto load_stage = [&](int s, int kt) {
        __half* Ap = As + s * GSTG;
        __half* Bp = Bs + s * GSTG;
#pragma unroll
        for (int j = 0; j < 2; j++) {
            int c = tid + 256 * j;
            int r = c >> 2, kc = c & 3;
            cpa16(Ap + r * GP + kc * 8, A  + (size_t)(row0 + r) * DD + kt * 32 + kc * 8);
            cpa16(Bp + r * GP + kc * 8, Wt + (size_t)(col0 + r) * DD + kt * 32 + kc * 8);
        }
    };

    const int NT = DD / 32;   // 32
    load_stage(0, 0); cpa_commit();
    load_stage(1, 1); cpa_commit();

    for (int it = 0; it < NT; it++) {
        cpa_wait1();
        __syncthreads();
        if (it + 2 < NT) load_stage((it + 2) % 3, it + 2);
        cpa_commit();

        const __half* Ac = As + (it % 3) * GSTG;
        const __half* Bc = Bs + (it % 3) * GSTG;
#pragma unroll
        for (int ks = 0; ks < 2; ks++) {
            const int k0 = ks * 16;
            unsigned a[2][4];
#pragma unroll
            for (int mt = 0; mt < 2; mt++)
                ldsm4(a[mt][0], a[mt][1], a[mt][2], a[mt][3],
                      Ac + (wm * 32 + mt * 16 + a_row) * GP + k0 + a_k);
            unsigned b[8][2];
#pragma unroll
            for (int np = 0; np < 4; np++)
                ldsm4(b[2 * np][0], b[2 * np][1], b[2 * np + 1][0], b[2 * np + 1][1],
                      Bc + (wn * 64 + np * 16 + b_row) * GP + k0 + b_k);
#pragma unroll
            for (int mt = 0; mt < 2; mt++)
#pragma unroll
                for (int nt = 0; nt < 8; nt++)
                    mma16(acc[mt][nt], a[mt], b[nt]);
        }
    }
}

// QKV batched projection: grid.z selects (A, Wt, bias, out16); z==0 also
// writes an fp32 residual copy and pre-scales fp16 out by log2e/8.
struct QkvArgs {
    const __half* A[3]; const __half* W[3]; const float* bias[3];
    __half* C16[3]; float* C32;
};

__global__ __launch_bounds__(256, 2) void qkv_gemm(QkvArgs ga)
{
    const int z = blockIdx.z;
    float acc[2][8][4];
    gemm16_core(ga.A[z], ga.W[z], acc);

    const int lane = threadIdx.x & 31;
    const int wid  = threadIdx.x >> 5;
    const int wm   = wid & 3, wn = wid >> 2;
    const int lq   = lane >> 2, lr = lane & 3;
    const int row0 = blockIdx.y * 128, col0 = blockIdx.x * 128;
    const float scale = (z == 0) ? 0.125f * 1.44269504f : 1.0f;
    const float* bias = ga.bias[z];
    __half* C16 = ga.C16[z];

#pragma unroll
    for (int mt = 0; mt < 2; mt++) {
#pragma unroll
        for (int nt = 0; nt < 8; nt++) {
            const int r  = row0 + wm * 32 + mt * 16 + lq;
            const int cb = col0 + wn * 64 + nt * 8 + 2 * lr;
            const float b0 = bias[cb], b1 = bias[cb + 1];
            float v00 = acc[mt][nt][0] + b0, v01 = acc[mt][nt][1] + b1;
            float v10 = acc[mt][nt][2] + b0, v11 = acc[mt][nt][3] + b1;
            *(__half2*)(C16 + (size_t)r * DD + cb) =
                __floats2half2_rn(v00 * scale, v01 * scale);
            *(__half2*)(C16 + (size_t)(r + 8) * DD + cb) =
                __floats2half2_rn(v10 * scale, v11 * scale);
            if (z == 0) {
                *(float2*)(ga.C32 + (size_t)r * DD + cb)       = make_float2(v00, v01);
                *(float2*)(ga.C32 + (size_t)(r + 8) * DD + cb) = make_float2(v10, v11);
            }
        }
    }
}

__global__ __launch_bounds__(256, 2) void fc_gemm(
    const __half* __restrict__ A, const __half* __restrict__ Wt,
    const float* __restrict__ bias, const float* __restrict__ res,
    float* __restrict__ C)
{
    float acc[2][8][4];
    gemm16_core(A, Wt, acc);

    const int lane = threadIdx.x & 31;
    const int wid  = threadIdx.x >> 5;
    const int wm   = wid & 3, wn = wid >> 2;
    const int lq   = lane >> 2, lr = lane & 3;
    const int row0 = blockIdx.y * 128, col0 = blockIdx.x * 128;

#pragma unroll
    for (int mt = 0; mt < 2; mt++) {
#pragma unroll
        for (int nt = 0; nt < 8; nt++) {
            const int r  = row0 + wm * 32 + mt * 16 + lq;
            const int cb = col0 + wn * 64 + nt * 8 + 2 * lr;
            const float b0 = bias[cb], b1 = bias[cb + 1];
            const float2 r0 = *(const float2*)(res + (size_t)r * DD + cb);
            const float2 r1 = *(const float2*)(res + (size_t)(r + 8) * DD + cb);
            *(float2*)(C + (size_t)r * DD + cb) =
                make_float2(acc[mt][nt][0] + b0 + r0.x, acc[mt][nt][1] + b1 + r0.y);
            *(float2*)(C + (size_t)(r + 8) * DD + cb) =
                make_float2(acc[mt][nt][2] + b0 + r1.x, acc[mt][nt][3] + b1 + r1.y);
        }
    }
}

// ----------------------------------------------------------------------------
// Flash attention, fp16 tensor cores, base-2 softmax with P IN REGISTERS.
// Block = (b*H+h, 128-row q tile), 256 threads (8 warps, 16 q-rows each).
// The S-accumulator C-fragment is repacked (via ex2.approx.f16x2) directly
// into the PV A-fragment: no P smem, ONE __syncthreads per iteration.
// 3-stage K/V ring; next tile's cp.async issued right after the S-mma.
// ----------------------------------------------------------------------------
#define AP 72
#define A_KSTG (64 * AP)
#define A_SMEM_HALVES (6 * A_KSTG)
#define A_SMEM_BYTES (A_SMEM_HALVES * 2)

__global__ __launch_bounds__(256, 2) void attn_tc(
    const __half* __restrict__ QP, const __half* __restrict__ KP,
    const __half* __restrict__ VP, __half* __restrict__ CTX)
{
    extern __shared__ __half asm16[];
    __half* KsBase = asm16;                    // 3 stages
    __half* VsBase = asm16 + 3 * A_KSTG;       // 3 stages

    const int tid  = threadIdx.x;
    const int lane = tid & 31;
    const int wid  = tid >> 5;       // 0..7
    const int lq   = lane >> 2;      // 0..7
    const int lr   = lane & 3;       // 0..3
    const int bh   = blockIdx.y;
    const int b    = bh >> 4;
    const int h    = bh & 15;
    const int q0   = blockIdx.x * 128;

    const int a_row = (lane & 7) + ((lane >> 3) & 1) * 8;
    const int a_k   = (lane >> 4) * 8;
    const int b_row = (lane & 7) + (lane >> 4) * 8;
    const int b_k   = ((lane >> 3) & 1) * 8;

    const __half* Kb = KP + (size_t)b * SS * DD + (size_t)h * 64;
    const __half* Vb = VP + (size_t)b * SS * DD + (size_t)h * 64;

    // Q fragments (pre-scaled by log2e/8 in projection epilogue)
    unsigned qf[4][4];
    {
        const int r = q0 + wid * 16 + lq;
        const __half* qptr = QP + (size_t)(b * SS + r) * DD + h * 64;
#pragma unroll
        for (int kk = 0; kk < 4; kk++) {
            const __half* p = qptr + kk * 16 + 2 * lr;
            qf[kk][0] = ldu32(p);
            qf[kk][1] = ldu32(p + (size_t)8 * DD);
            qf[kk][2] = ldu32(p + 8);
            qf[kk][3] = ldu32(p + (size_t)8 * DD + 8);
        }
    }

    float o[8][4];
#pragma unroll
    for (int nt = 0; nt < 8; nt++)
#pragma unroll
        for (int c = 0; c < 4; c++) o[nt][c] = 0.f;
    float mrow[2] = {-INFINITY, -INFINITY};
    float lrow[2] = {0.f, 0.f};

    auto load_kv = [&](int s, int kt) {
        __half* Ks = KsBase + s * A_KSTG;
        __half* Vs = VsBase + s * A_KSTG;
#pragma unroll
        for (int j = 0; j < 2; j++) {
            int c = tid + 256 * j;        // 0..511
            int r = c >> 3, kc = c & 7;
            const size_t goff = (size_t)(kt * 64 + r) * DD + kc * 8;
            cpa16(Ks + r * AP + kc * 8, Kb + goff);
            cpa16(Vs + r * AP + kc * 8, Vb + goff);
        }
    };

    const int NT = SS / 64;   // 32
    load_kv(0, 0); cpa_commit();
    load_kv(1, 1); cpa_commit();

    for (int kt = 0; kt < NT; kt++) {
        cpa_wait1();
        __syncthreads();   // stage kt ready; all warps fully done with iter kt-1
        const int st = kt % 3;
        const __half* Kc = KsBase + st * A_KSTG;
        const __half* Vc = VsBase + st * A_KSTG;

        // S = (log2e/8 * Q) K^T : 16x64 per warp (base-2 logits)
        float sacc[8][4];
#pragma unroll
        for (int nt = 0; nt < 8; nt++)
#pragma unroll
            for (int c = 0; c < 4; c++) sacc[nt][c] = 0.f;
#pragma unroll
        for (int kk = 0; kk < 4; kk++) {
            unsigned kb[8][2];
#pragma unroll
            for (int np = 0; np < 4; np++)
                ldsm4(kb[2 * np][0], kb[2 * np][1], kb[2 * np + 1][0], kb[2 * np + 1][1],
                      Kc + (np * 16 + b_row) * AP + kk * 16 + b_k);
#pragma unroll
            for (int nt = 0; nt < 8; nt++)
                mma16(sacc[nt], qf[kk], kb[nt]);
        }

        // prefetch next tile under softmax+PV (stage (kt+2)%3 is idle:
        // it held iter kt-1's data, finished before the sync above)
        if (kt + 2 < NT) { load_kv((kt + 2) % 3, kt + 2); }
        cpa_commit();

        // base-2 online softmax; P packed to fp16 PV A-fragments in registers
        float mx0 = -INFINITY, mx1 = -INFINITY;
#pragma unroll
        for (int nt = 0; nt < 8; nt++) {
            mx0 = fmaxf(mx0, fmaxf(sacc[nt][0], sacc[nt][1]));
            mx1 = fmaxf(mx1, fmaxf(sacc[nt][2], sacc[nt][3]));
        }
        mx0 = fmaxf(mx0, __shfl_xor_sync(0xffffffffu, mx0, 1));
        mx0 = fmaxf(mx0, __shfl_xor_sync(0xffffffffu, mx0, 2));
        mx1 = fmaxf(mx1, __shfl_xor_sync(0xffffffffu, mx1, 1));
        mx1 = fmaxf(mx1, __shfl_xor_sync(0xffffffffu, mx1, 2));
        {
            const bool ch0 = mx0 > mrow[0], ch1 = mx1 > mrow[1];
            const float m0 = ch0 ? mx0 : mrow[0];
            const float m1 = ch1 ? mx1 : mrow[1];
            if (__any_sync(0xffffffffu, ch0 | ch1)) {
                const float al0 = exp2f(mrow[0] - m0);
                const float al1 = exp2f(mrow[1] - m1);
                lrow[0] *= al0; lrow[1] *= al1;
#pragma unroll
                for (int nt = 0; nt < 8; nt++) {
                    o[nt][0] *= al0; o[nt][1] *= al0;
                    o[nt][2] *= al1; o[nt][3] *= al1;
                }
                mrow[0] = m0; mrow[1] = m1;
            }
        }

        unsigned pfrag[4][4];
        float ps0 = 0.f, ps1 = 0.f;
#pragma unroll
        for (int nt = 0; nt < 8; nt++) {
            __half2 d0 = __floats2half2_rn(sacc[nt][0] - mrow[0],
                                           sacc[nt][1] - mrow[0]);
            __half2 d1 = __floats2half2_rn(sacc[nt][2] - mrow[1],
                                           sacc[nt][3] - mrow[1]);
            unsigned e0 = h2exp2u(*(unsigned*)&d0);
            unsigned e1 = h2exp2u(*(unsigned*)&d1);
            pfrag[nt >> 1][(nt & 1) * 2 + 0] = e0;
            pfrag[nt >> 1][(nt & 1) * 2 + 1] = e1;
            float2 f0 = __half22float2(*(__half2*)&e0);
            float2 f1 = __half22float2(*(__half2*)&e1);
            ps0 += f0.x + f0.y;
            ps1 += f1.x + f1.y;
        }
        ps0 += __shfl_xor_sync(0xffffffffu, ps0, 1);
        ps0 += __shfl_xor_sync(0xffffffffu, ps0, 2);
        ps1 += __shfl_xor_sync(0xffffffffu, ps1, 1);
        ps1 += __shfl_xor_sync(0xffffffffu, ps1, 2);
        lrow[0] += ps0;
        lrow[1] += ps1;

        // O += P V  (P already in A-fragment registers; V via ldmatrix.trans)
#pragma unroll
        for (int kk = 0; kk < 4; kk++) {
            unsigned vb[8][2];
#pragma unroll
            for (int np = 0; np < 4; np++)
                ldsm4t(vb[2 * np][0], vb[2 * np][1], vb[2 * np + 1][0], vb[2 * np + 1][1],
                       Vc + (kk * 16 + a_row) * AP + np * 16 + a_k);
#pragma unroll
            for (int nt = 0; nt < 8; nt++)
                mma16(o[nt], pfrag[kk], vb[nt]);
        }
    }

    // epilogue: normalize, store ctx fp16 in [B,S,H*DV]
    {
        const float inv0 = 1.f / lrow[0];
        const float inv1 = 1.f / lrow[1];
        const int r0 = q0 + wid * 16 + lq;
#pragma unroll
        for (int nt = 0; nt < 8; nt++) {
            const int col = h * 64 + nt * 8 + 2 * lr;
            *(__half2*)(CTX + (size_t)(b * SS + r0) * DD + col) =
                __floats2half2_rn(o[nt][0] * inv0, o[nt][1] * inv0);
            *(__half2*)(CTX + (size_t)(b * SS + r0 + 8) * DD + col) =
                __floats2half2_rn(o[nt][2] * inv1, o[nt][3] * inv1);
        }
    }
}

// ----------------------------------------------------------------------------
// LayerNorm: one block per row
// ----------------------------------------------------------------------------
__global__ __launch_bounds__(256) void ln_kernel(
    const float* __restrict__ X, const float* __restrict__ gamma,
    const float* __restrict__ beta, float* __restrict__ out)
{
    __shared__ float sh[18];
    const int row = blockIdx.x;
    const int tid = threadIdx.x;
    const float* xr = X + (size_t)row * DD;
    float4 v = *(const float4*)(xr + tid * 4);
    float s  = v.x + v.y + v.z + v.w;
    float sq = v.x * v.x + v.y * v.y + v.z * v.z + v.w * v.w;
#pragma unroll
    for (int off = 16; off; off >>= 1) {
        s  += __shfl_xor_sync(0xffffffffu, s, off);
        sq += __shfl_xor_sync(0xffffffffu, sq, off);
    }
    const int warp = tid >> 5;
    if ((tid & 31) == 0) { sh[warp] = s; sh[8 + warp] = sq; }
    __syncthreads();
    if (tid == 0) {
        float ts = 0.f, tq = 0.f;
#pragma unroll
        for (int w = 0; w < 8; w++) { ts += sh[w]; tq += sh[8 + w]; }
        float mu = ts * (1.f / DD);
        float var = tq * (1.f / DD) - mu * mu;
        sh[16] = mu;
        sh[17] = rsqrtf(var + 1e-5f);
    }
    __syncthreads();
    const float mu = sh[16], rstd = sh[17];
    float4 g = *(const float4*)(gamma + tid * 4);
    float4 bt = *(const float4*)(beta + tid * 4);
    float4 o;
    o.x = (v.x - mu) * rstd * g.x + bt.x;
    o.y = (v.y - mu) * rstd * g.y + bt.y;
    o.z = (v.z - mu) * rstd * g.z + bt.z;
    o.w = (v.w - mu) * rstd * g.w + bt.w;
    *(float4*)(out + (size_t)row * DD + tid * 4) = o;
}

// ----------------------------------------------------------------------------
// Launch
// ----------------------------------------------------------------------------
extern "C" void kernel_launch(void* const* d_in, const int* in_sizes, int n_in,
                              void* d_out, int out_size)
{
    const float* q     = (const float*)d_in[0];
    const float* k     = (const float*)d_in[1];
    const float* v     = (const float*)d_in[2];
    const float* Wq    = (const float*)d_in[3];
    const float* bq    = (const float*)d_in[4];
    const float* Wk    = (const float*)d_in[5];
    const float* bk    = (const float*)d_in[6];
    const float* Wv    = (const float*)d_in[7];
    const float* bv    = (const float*)d_in[8];
    const float* Wfc   = (const float*)d_in[9];
    const float* bfc   = (const float*)d_in[10];
    const float* gamma = (const float*)d_in[11];
    const float* beta  = (const float*)d_in[12];
    float* out = (float*)d_out;

    __half *q16, *k16, *v16, *qp16, *kp16, *vp16, *ctx16, *wq, *wk, *wv, *wfc;
    float *qp32, *xres;
    cudaGetSymbolAddress((void**)&q16,   g_q16);
    cudaGetSymbolAddress((void**)&k16,   g_k16);
    cudaGetSymbolAddress((void**)&v16,   g_v16);
    cudaGetSymbolAddress((void**)&qp16,  g_qp16);
    cudaGetSymbolAddress((void**)&kp16,  g_kp16);
    cudaGetSymbolAddress((void**)&vp16,  g_vp16);
    cudaGetSymbolAddress((void**)&ctx16, g_ctx16);
    cudaGetSymbolAddress((void**)&qp32,  g_qp32);
    cudaGetSymbolAddress((void**)&xres,  g_x);
    cudaGetSymbolAddress((void**)&wq,    g_wq);
    cudaGetSymbolAddress((void**)&wk,    g_wk);
    cudaGetSymbolAddress((void**)&wv,    g_wv);
    cudaGetSymbolAddress((void**)&wfc,   g_wfc);

    cudaFuncSetAttribute(qkv_gemm, cudaFuncAttributeMaxDynamicSharedMemorySize,
                         G_SMEM_BYTES);
    cudaFuncSetAttribute(fc_gemm, cudaFuncAttributeMaxDynamicSharedMemorySize,
                         G_SMEM_BYTES);
    cudaFuncSetAttribute(attn_tc, cudaFuncAttributeMaxDynamicSharedMemorySize,
                         A_SMEM_BYTES);

    // fp16 input conversion (batched q/k/v)
    CvtIn ci;
    ci.in[0] = q; ci.out[0] = q16;
    ci.in[1] = k; ci.out[1] = k16;
    ci.in[2] = v; ci.out[2] = v16;
    const int n4 = NELEM / 4;
    cvt_in_kernel<<<dim3(n4 / 256, 3), 256>>>(ci, n4);

    // fp16 transposed weight conversion (batched 4 weights)
    CvtW cw;
    cw.in[0] = Wq;  cw.out[0] = wq;
    cw.in[1] = Wk;  cw.out[1] = wk;
    cw.in[2] = Wv;  cw.out[2] = wv;
    cw.in[3] = Wfc; cw.out[3] = wfc;
    cvt_wt_kernel<<<dim3(DD / 32, DD / 32, 4), 256>>>(cw);

    // batched QKV projections
    QkvArgs ga;
    ga.A[0] = q16; ga.W[0] = wq; ga.bias[0] = bq; ga.C16[0] = qp16;
    ga.A[1] = k16; ga.W[1] = wk; ga.bias[1] = bk; ga.C16[1] = kp16;
    ga.A[2] = v16; ga.W[2] = wv; ga.bias[2] = bv; ga.C16[2] = vp16;
    ga.C32 = qp32;
    qkv_gemm<<<dim3(DD / 128, BS / 128, 3), 256, G_SMEM_BYTES>>>(ga);

    attn_tc<<<dim3(SS / 128, BB * HH), 256, A_SMEM_BYTES>>>(qp16, kp16, vp16, ctx16);

    fc_gemm<<<dim3(DD / 128, BS / 128), 256, G_SMEM_BYTES>>>(ctx16, wfc, bfc, qp32, xres);

    ln_kernel<<<BS, 256>>>(xres, gamma, beta, out);
}